// round 4
// baseline (speedup 1.0000x reference)
#include <cuda_runtime.h>
#include <cuda_bf16.h>
#include <cstdint>

#define NTOK   294
#define HEADS  8
#define DH     32
#define DIM    256
#define NWIN   256
#define NBIAS  1859
#define QSCALE 0.17677669529663687f  // 32^-0.5
#define XSZ    (6 * 16 * 16 * 7 * 7 * 256)   // 19267584

// ---------------- scratch (allocation-free: __device__ globals) -------------
__device__ float g_q[NWIN * HEADS * NTOK * DH];
__device__ float g_k[NWIN * HEADS * NTOK * DH];
__device__ float g_v[NWIN * HEADS * NTOK * DH];
__device__ __nv_bfloat16 g_x_hi[XSZ];
__device__ __nv_bfloat16 g_x_lo[XSZ];
__device__ __nv_bfloat16 g_wq_hi[768 * 256];
__device__ __nv_bfloat16 g_wq_lo[768 * 256];
__device__ __nv_bfloat16 g_wo_hi[256 * 256];
__device__ __nv_bfloat16 g_wo_lo[256 * 256];
__device__ __nv_bfloat16 g_oh[NWIN * NTOK * DIM];
__device__ __nv_bfloat16 g_ol[NWIN * NTOK * DIM];

// ---------------- helpers ---------------------------------------------------
__device__ __forceinline__ uint32_t smem_u32(const void* p) {
    uint32_t a;
    asm("{ .reg .u64 t; cvta.to.shared.u64 t, %1; cvt.u32.u64 %0, t; }" : "=r"(a) : "l"(p));
    return a;
}

#define LDSM4(r, a) \
    asm volatile("ldmatrix.sync.aligned.m8n8.x4.shared.b16 {%0,%1,%2,%3}, [%4];" \
        : "=r"((r)[0]), "=r"((r)[1]), "=r"((r)[2]), "=r"((r)[3]) : "r"(a))

#define MMA16816(d, a, b0, b1) \
    asm volatile("mma.sync.aligned.m16n8k16.row.col.f32.bf16.bf16.f32 " \
        "{%0,%1,%2,%3}, {%4,%5,%6,%7}, {%8,%9}, {%0,%1,%2,%3};" \
        : "+f"((d)[0]), "+f"((d)[1]), "+f"((d)[2]), "+f"((d)[3]) \
        : "r"((a)[0]), "r"((a)[1]), "r"((a)[2]), "r"((a)[3]), "r"(b0), "r"(b1))

__device__ __forceinline__ uint16_t bfu(__nv_bfloat16 h) { return __bfloat16_as_ushort(h); }

// split float4 into packed hi/lo bf16 (2x uint2)
__device__ __forceinline__ void split_pack(float4 v, uint2& hi, uint2& lo) {
    __nv_bfloat16 h0 = __float2bfloat16_rn(v.x);
    __nv_bfloat16 h1 = __float2bfloat16_rn(v.y);
    __nv_bfloat16 h2 = __float2bfloat16_rn(v.z);
    __nv_bfloat16 h3 = __float2bfloat16_rn(v.w);
    __nv_bfloat16 l0 = __float2bfloat16_rn(v.x - __bfloat162float(h0));
    __nv_bfloat16 l1 = __float2bfloat16_rn(v.y - __bfloat162float(h1));
    __nv_bfloat16 l2 = __float2bfloat16_rn(v.z - __bfloat162float(h2));
    __nv_bfloat16 l3 = __float2bfloat16_rn(v.w - __bfloat162float(h3));
    hi = make_uint2((uint32_t)bfu(h0) | ((uint32_t)bfu(h1) << 16),
                    (uint32_t)bfu(h2) | ((uint32_t)bfu(h3) << 16));
    lo = make_uint2((uint32_t)bfu(l0) | ((uint32_t)bfu(l1) << 16),
                    (uint32_t)bfu(l2) | ((uint32_t)bfu(l3) << 16));
}

// smem tile layout: 128 rows x 64 bf16 (128B/row), XOR swizzle on 16B groups
#define T_AHI 0
#define T_ALO 16384
#define T_BHI 32768
#define T_BLO 49152
#define SM_RB 65536                     // 128 ints (qkv rowbase)
#define SM_GEMM_TOTAL (65536 + 512)

// ---------------- prep kernels ----------------------------------------------
__global__ __launch_bounds__(256) void split_x_kernel(const float* __restrict__ x)
{
    int i = blockIdx.x * blockDim.x + threadIdx.x;   // one float4 per thread
    if (i < XSZ / 4) {
        float4 v = ((const float4*)x)[i];
        uint2 hi, lo;
        split_pack(v, hi, lo);
        ((uint2*)g_x_hi)[i] = hi;
        ((uint2*)g_x_lo)[i] = lo;
    }
}

__global__ __launch_bounds__(256) void split_w_kernel(const float* __restrict__ wqkv,
                                                      const float* __restrict__ wout)
{
    int i = blockIdx.x * blockDim.x + threadIdx.x;   // one float4 per thread
    const int NQ4 = 768 * 256 / 4;
    const int NO4 = 256 * 256 / 4;
    if (i < NQ4) {
        float4 v = ((const float4*)wqkv)[i];
        uint2 hi, lo;
        split_pack(v, hi, lo);
        ((uint2*)g_wq_hi)[i] = hi;
        ((uint2*)g_wq_lo)[i] = lo;
    } else if (i < NQ4 + NO4) {
        int j = i - NQ4;
        float4 v = ((const float4*)wout)[j];
        uint2 hi, lo;
        split_pack(v, hi, lo);
        ((uint2*)g_wo_hi)[j] = hi;
        ((uint2*)g_wo_lo)[j] = lo;
    }
}

// ---------------------------------------------------------------------------
// Kernel 1: QKV GEMM via mma.sync bf16 3-pass. grid (6, 3, 256), block 256.
// C[384pad x 768] = A[294 x 256] @ Wqkv^T.  CTA tile 128x128, warp 32x64.
// ---------------------------------------------------------------------------
__global__ __launch_bounds__(256) void qkv_kernel()
{
    extern __shared__ char sm[];
    const uint32_t smb = smem_u32(sm);
    int* rb = (int*)(sm + SM_RB);

    const int bx = blockIdx.x;      // n-chunk (0..5)
    const int by = blockIdx.y;      // m-tile (0..2)
    const int w  = blockIdx.z;      // window
    const int tid = threadIdx.x;
    const int lane = tid & 31, wid = tid >> 5;
    const int wm = wid & 3, wn = wid >> 2;
    const int hx = w >> 4, wy = w & 15;

    if (tid < 128) {
        int n = by * 128 + tid;
        if (n < NTOK) {
            int l = n / 49; int rem = n - l * 49; int w1 = rem / 7; int w2 = rem - w1 * 7;
            rb[tid] = ((l * 256 + hx * 16 + wy) * 49 + w1 * 7 + w2) * 256;
        } else rb[tid] = -1;
    }
    __syncthreads();

    float acc[2][8][4];
    #pragma unroll
    for (int mt = 0; mt < 2; mt++)
        #pragma unroll
        for (int nt = 0; nt < 8; nt++)
            #pragma unroll
            for (int r = 0; r < 4; r++) acc[mt][nt][r] = 0.f;

    // per-lane ldmatrix address components
    const int l7 = lane & 7;
    const uint32_t arow0 = (uint32_t)(wm * 32 + (lane & 15)) * 128;
    const int cgA = lane >> 4;
    const int g = lane >> 3;
    const uint32_t brow0 = (uint32_t)(wn * 64 + ((g & 2) << 2) + l7) * 128;
    const int cgB = g & 1;

    for (int chunk = 0; chunk < 4; chunk++) {
        // ---- stage 4 tiles (A_hi, A_lo, B_hi, B_lo), 16B units, swizzled ----
        #pragma unroll
        for (int i = 0; i < 16; i++) {
            int u = tid + i * 256;          // 0..4095
            int tile = u >> 10;
            int uu = u & 1023;
            int row = uu >> 3, kg = uu & 7;
            char* dst = sm + (tile << 14) + row * 128 + ((kg ^ (row & 7)) << 4);
            uint4 val = make_uint4(0u, 0u, 0u, 0u);
            if (tile < 2) {
                int base = rb[row];
                if (base >= 0) {
                    const __nv_bfloat16* src = (tile == 0 ? g_x_hi : g_x_lo)
                                               + base + chunk * 64 + kg * 8;
                    val = *(const uint4*)src;
                }
            } else {
                int nrow = bx * 128 + row;
                const __nv_bfloat16* src = (tile == 2 ? g_wq_hi : g_wq_lo)
                                           + nrow * 256 + chunk * 64 + kg * 8;
                val = *(const uint4*)src;
            }
            *(uint4*)dst = val;
        }
        __syncthreads();

        #pragma unroll
        for (int pass = 0; pass < 3; pass++) {
            const uint32_t Ab = smb + (pass == 1 ? T_ALO : T_AHI);
            const uint32_t Bb = smb + (pass == 2 ? T_BLO : T_BHI);
            #pragma unroll
            for (int ks = 0; ks < 4; ks++) {
                uint32_t a[2][4];
                uint32_t aswz = (uint32_t)((ks * 2 + cgA) ^ l7) << 4;
                LDSM4(a[0], Ab + arow0 + aswz);
                LDSM4(a[1], Ab + arow0 + 2048 + aswz);
                uint32_t b[4][4];
                uint32_t bswz = (uint32_t)((ks * 2 + cgB) ^ l7) << 4;
                #pragma unroll
                for (int p = 0; p < 4; p++)
                    LDSM4(b[p], Bb + brow0 + p * 2048 + bswz);
                #pragma unroll
                for (int mt = 0; mt < 2; mt++)
                    #pragma unroll
                    for (int nt = 0; nt < 8; nt++)
                        MMA16816(acc[mt][nt], a[mt], b[nt >> 1][(nt & 1) * 2],
                                 b[nt >> 1][(nt & 1) * 2 + 1]);
            }
        }
        __syncthreads();
    }

    // ---- epilogue: scatter to g_q / g_k / g_v -------------------------------
    const int part = bx >> 1;                         // 0=q 1=k 2=v (128-chunks)
    float* dstbuf = (part == 0) ? g_q : (part == 1) ? g_k : g_v;
    const float scale = (part == 0) ? QSCALE : 1.f;
    const int trow = lane >> 2;
    const int tcol2 = (lane & 3) * 2;

    #pragma unroll
    for (int mt = 0; mt < 2; mt++) {
        #pragma unroll
        for (int half = 0; half < 2; half++) {
            int r = by * 128 + wm * 32 + mt * 16 + trow + half * 8;
            if (r >= NTOK) continue;
            #pragma unroll
            for (int nt = 0; nt < 8; nt++) {
                int o = bx * 128 + wn * 64 + nt * 8 + tcol2;
                int h = (o & 255) >> 5, d = o & 31;
                float2 v = make_float2(acc[mt][nt][half * 2] * scale,
                                       acc[mt][nt][half * 2 + 1] * scale);
                *(float2*)(dstbuf + ((size_t)(w * 8 + h) * NTOK + r) * 32 + d) = v;
            }
        }
    }
}

// ---------------------------------------------------------------------------
// Kernel 2: attention per (window, head). 2048 blocks, 160 threads.
// Unchanged math; output written as bf16 hi/lo for the out-GEMM.
// ---------------------------------------------------------------------------
__global__ __launch_bounds__(160) void attn_kernel(const float* __restrict__ bias_table)
{
    extern __shared__ float smf[];
    float4* K4 = (float4*)smf;                        // 2352 float4
    float4* V4 = K4 + (NTOK * DH / 4);                // 2352 float4
    float*  bH = smf + 2 * NTOK * DH;                 // 1859 floats
    int*    cj = (int*)(bH + NBIAS);                  // 294 ints

    const int wh  = blockIdx.x;
    const int h   = wh & 7;
    const int w   = wh >> 3;
    const int tid = threadIdx.x;

    const float4* gK = (const float4*)(g_k + (size_t)wh * NTOK * DH);
    const float4* gV = (const float4*)(g_v + (size_t)wh * NTOK * DH);
    for (int i = tid; i < NTOK * DH / 4; i += 160) { K4[i] = gK[i]; V4[i] = gV[i]; }
    for (int i = tid; i < NBIAS; i += 160) bH[i] = bias_table[i * HEADS + h];
    for (int i = tid; i < NTOK; i += 160) {
        int l = i / 49, rem = i - l * 49, w1 = rem / 7, w2 = rem - w1 * 7;
        cj[i] = l * 169 + w1 * 13 + w2;
    }
    __syncthreads();

    const int r1 = tid;
    const int r2 = tid + 160;
    const bool v2 = (r2 < NTOK);

    float q1[32], q2[32];
    const float4* gQ = (const float4*)(g_q + (size_t)wh * NTOK * DH);
    #pragma unroll
    for (int kk = 0; kk < 8; kk++) {
        float4 a = gQ[r1 * 8 + kk];
        q1[4*kk+0] = a.x; q1[4*kk+1] = a.y; q1[4*kk+2] = a.z; q1[4*kk+3] = a.w;
        float4 b = v2 ? gQ[r2 * 8 + kk] : make_float4(0.f, 0.f, 0.f, 0.f);
        q2[4*kk+0] = b.x; q2[4*kk+1] = b.y; q2[4*kk+2] = b.z; q2[4*kk+3] = b.w;
    }

    float acc1[32], acc2[32];
    #pragma unroll
    for (int d = 0; d < 32; d++) { acc1[d] = 0.f; acc2[d] = 0.f; }
    float s1 = 0.f, s2 = 0.f;
    const int ci1 = cj[r1] + 929;
    const int ci2 = v2 ? (cj[r2] + 929) : 929;

    for (int j = 0; j < NTOK; j++) {
        int cjj = cj[j];
        float a0 = 0.f, a1 = 0.f, a2 = 0.f, a3 = 0.f;
        float e0 = 0.f, e1 = 0.f, e2 = 0.f, e3 = 0.f;
        #pragma unroll
        for (int kk = 0; kk < 8; kk++) {
            float4 kv = K4[j * 8 + kk];
            a0 += q1[4*kk+0] * kv.x;
            a1 += q1[4*kk+1] * kv.y;
            a2 += q1[4*kk+2] * kv.z;
            a3 += q1[4*kk+3] * kv.w;
            e0 += q2[4*kk+0] * kv.x;
            e1 += q2[4*kk+1] * kv.y;
            e2 += q2[4*kk+2] * kv.z;
            e3 += q2[4*kk+3] * kv.w;
        }
        float d1 = (a0 + a1) + (a2 + a3);
        float d2 = (e0 + e1) + (e2 + e3);
        float p1 = __expf(d1 + bH[ci1 - cjj]);
        float p2 = __expf(d2 + bH[ci2 - cjj]);
        s1 += p1; s2 += p2;
        #pragma unroll
        for (int kk = 0; kk < 8; kk++) {
            float4 vv = V4[j * 8 + kk];
            acc1[4*kk+0] += p1 * vv.x;  acc1[4*kk+1] += p1 * vv.y;
            acc1[4*kk+2] += p1 * vv.z;  acc1[4*kk+3] += p1 * vv.w;
            acc2[4*kk+0] += p2 * vv.x;  acc2[4*kk+1] += p2 * vv.y;
            acc2[4*kk+2] += p2 * vv.z;  acc2[4*kk+3] += p2 * vv.w;
        }
    }

    {
        float inv = 1.f / s1;
        size_t base = ((size_t)w * NTOK + r1) * DIM + h * DH;
        #pragma unroll
        for (int kk = 0; kk < 8; kk++) {
            float4 v = make_float4(acc1[4*kk+0]*inv, acc1[4*kk+1]*inv,
                                   acc1[4*kk+2]*inv, acc1[4*kk+3]*inv);
            uint2 hi, lo;
            split_pack(v, hi, lo);
            *(uint2*)(g_oh + base + kk * 4) = hi;
            *(uint2*)(g_ol + base + kk * 4) = lo;
        }
    }
    if (v2) {
        float inv = 1.f / s2;
        size_t base = ((size_t)w * NTOK + r2) * DIM + h * DH;
        #pragma unroll
        for (int kk = 0; kk < 8; kk++) {
            float4 v = make_float4(acc2[4*kk+0]*inv, acc2[4*kk+1]*inv,
                                   acc2[4*kk+2]*inv, acc2[4*kk+3]*inv);
            uint2 hi, lo;
            split_pack(v, hi, lo);
            *(uint2*)(g_oh + base + kk * 4) = hi;
            *(uint2*)(g_ol + base + kk * 4) = lo;
        }
    }
}

// ---------------------------------------------------------------------------
// Kernel 3: output GEMM via mma.sync bf16 3-pass. grid (2, 3, 256), block 256.
// C[384pad x 256] = O[294 x 256] @ Wout^T, scattered to (b l x y w1 w2 d).
// ---------------------------------------------------------------------------
__global__ __launch_bounds__(256) void out_kernel(float* __restrict__ out)
{
    extern __shared__ char sm[];
    const uint32_t smb = smem_u32(sm);

    const int bx = blockIdx.x;      // n-chunk (0..1)
    const int by = blockIdx.y;      // m-tile (0..2)
    const int w  = blockIdx.z;
    const int tid = threadIdx.x;
    const int lane = tid & 31, wid = tid >> 5;
    const int wm = wid & 3, wn = wid >> 2;
    const int hx = w >> 4, wy = w & 15;

    float acc[2][8][4];
    #pragma unroll
    for (int mt = 0; mt < 2; mt++)
        #pragma unroll
        for (int nt = 0; nt < 8; nt++)
            #pragma unroll
            for (int r = 0; r < 4; r++) acc[mt][nt][r] = 0.f;

    const int l7 = lane & 7;
    const uint32_t arow0 = (uint32_t)(wm * 32 + (lane & 15)) * 128;
    const int cgA = lane >> 4;
    const int g = lane >> 3;
    const uint32_t brow0 = (uint32_t)(wn * 64 + ((g & 2) << 2) + l7) * 128;
    const int cgB = g & 1;

    for (int chunk = 0; chunk < 4; chunk++) {
        #pragma unroll
        for (int i = 0; i < 16; i++) {
            int u = tid + i * 256;
            int tile = u >> 10;
            int uu = u & 1023;
            int row = uu >> 3, kg = uu & 7;
            char* dst = sm + (tile << 14) + row * 128 + ((kg ^ (row & 7)) << 4);
            uint4 val = make_uint4(0u, 0u, 0u, 0u);
            if (tile < 2) {
                int tok = by * 128 + row;
                if (tok < NTOK) {
                    const __nv_bfloat16* src = (tile == 0 ? g_oh : g_ol)
                        + ((size_t)w * NTOK + tok) * DIM + chunk * 64 + kg * 8;
                    val = *(const uint4*)src;
                }
            } else {
                int nrow = bx * 128 + row;
                const __nv_bfloat16* src = (tile == 2 ? g_wo_hi : g_wo_lo)
                                           + nrow * 256 + chunk * 64 + kg * 8;
                val = *(const uint4*)src;
            }
            *(uint4*)dst = val;
        }
        __syncthreads();

        #pragma unroll
        for (int pass = 0; pass < 3; pass++) {
            const uint32_t Ab = smb + (pass == 1 ? T_ALO : T_AHI);
            const uint32_t Bb = smb + (pass == 2 ? T_BLO : T_BHI);
            #pragma unroll
            for (int ks = 0; ks < 4; ks++) {
                uint32_t a[2][4];
                uint32_t aswz = (uint32_t)((ks * 2 + cgA) ^ l7) << 4;
                LDSM4(a[0], Ab + arow0 + aswz);
                LDSM4(a[1], Ab + arow0 + 2048 + aswz);
                uint32_t b[4][4];
                uint32_t bswz = (uint32_t)((ks * 2 + cgB) ^ l7) << 4;
                #pragma unroll
                for (int p = 0; p < 4; p++)
                    LDSM4(b[p], Bb + brow0 + p * 2048 + bswz);
                #pragma unroll
                for (int mt = 0; mt < 2; mt++)
                    #pragma unroll
                    for (int nt = 0; nt < 8; nt++)
                        MMA16816(acc[mt][nt], a[mt], b[nt >> 1][(nt & 1) * 2],
                                 b[nt >> 1][(nt & 1) * 2 + 1]);
            }
        }
        __syncthreads();
    }

    const int trow = lane >> 2;
    const int tcol2 = (lane & 3) * 2;
    #pragma unroll
    for (int mt = 0; mt < 2; mt++) {
        #pragma unroll
        for (int half = 0; half < 2; half++) {
            int r = by * 128 + wm * 32 + mt * 16 + trow + half * 8;
            if (r >= NTOK) continue;
            int l = r / 49; int rem = r - l * 49; int w1 = rem / 7; int w2 = rem - w1 * 7;
            int ob = ((l * 256 + hx * 16 + wy) * 49 + w1 * 7 + w2) * 256;
            #pragma unroll
            for (int nt = 0; nt < 8; nt++) {
                int o = bx * 128 + wn * 64 + nt * 8 + tcol2;
                *(float2*)(out + ob + o) = make_float2(acc[mt][nt][half * 2],
                                                       acc[mt][nt][half * 2 + 1]);
            }
        }
    }
}

// ---------------------------------------------------------------------------
extern "C" void kernel_launch(void* const* d_in, const int* in_sizes, int n_in,
                              void* d_out, int out_size)
{
    const float* x    = (const float*)d_in[0];   // [1,6,16,16,7,7,256]
    const float* wqkv = (const float*)d_in[1];   // [768,256]
    const float* wout = (const float*)d_in[2];   // [256,256]
    const float* bias = (const float*)d_in[3];   // [1859,8]
    float* out = (float*)d_out;

    const int attn_smem = (2 * NTOK * DH + NBIAS + NTOK) * (int)sizeof(float);
    cudaFuncSetAttribute(attn_kernel, cudaFuncAttributeMaxDynamicSharedMemorySize, attn_smem);
    cudaFuncSetAttribute(qkv_kernel, cudaFuncAttributeMaxDynamicSharedMemorySize, SM_GEMM_TOTAL);
    cudaFuncSetAttribute(out_kernel, cudaFuncAttributeMaxDynamicSharedMemorySize, SM_GEMM_TOTAL);

    split_x_kernel<<<(XSZ / 4 + 255) / 256, 256>>>(x);
    split_w_kernel<<<(768 * 256 / 4 + 256 * 256 / 4 + 255) / 256, 256>>>(wqkv, wout);
    qkv_kernel<<<dim3(6, 3, 256), 256, SM_GEMM_TOTAL>>>();
    attn_kernel<<<2048, 160, attn_smem>>>(bias);
    out_kernel<<<dim3(2, 3, 256), 256, SM_GEMM_TOTAL>>>(out);
}

// round 5
// speedup vs baseline: 1.5257x; 1.5257x over previous
#include <cuda_runtime.h>
#include <cuda_bf16.h>
#include <cstdint>

#define NTOK   294
#define HEADS  8
#define DH     32
#define DIM    256
#define NWIN   256
#define NBIAS  1859
#define QSCALE 0.17677669529663687f  // 32^-0.5
#define XSZ    (6 * 16 * 16 * 7 * 7 * 256)   // 19267584

// ---------------- scratch (allocation-free: __device__ globals) -------------
__device__ float g_q[NWIN * HEADS * NTOK * DH];
__device__ float g_k[NWIN * HEADS * NTOK * DH];
__device__ float g_v[NWIN * HEADS * NTOK * DH];
__device__ float g_o[NWIN * NTOK * DIM];
__device__ __nv_bfloat16 g_x_hi[XSZ];
__device__ __nv_bfloat16 g_x_lo[XSZ];
__device__ __nv_bfloat16 g_wq_hi[768 * 256];
__device__ __nv_bfloat16 g_wq_lo[768 * 256];
__device__ __nv_bfloat16 g_wo_hi[256 * 256];
__device__ __nv_bfloat16 g_wo_lo[256 * 256];

// ---------------- helpers ---------------------------------------------------
__device__ __forceinline__ uint32_t smem_u32(const void* p) {
    uint32_t a;
    asm("{ .reg .u64 t; cvta.to.shared.u64 t, %1; cvt.u32.u64 %0, t; }" : "=r"(a) : "l"(p));
    return a;
}

#define LDSM4(r, a) \
    asm volatile("ldmatrix.sync.aligned.m8n8.x4.shared.b16 {%0,%1,%2,%3}, [%4];" \
        : "=r"((r)[0]), "=r"((r)[1]), "=r"((r)[2]), "=r"((r)[3]) : "r"(a))

#define MMA16816(d, a, b0, b1) \
    asm volatile("mma.sync.aligned.m16n8k16.row.col.f32.bf16.bf16.f32 " \
        "{%0,%1,%2,%3}, {%4,%5,%6,%7}, {%8,%9}, {%0,%1,%2,%3};" \
        : "+f"((d)[0]), "+f"((d)[1]), "+f"((d)[2]), "+f"((d)[3]) \
        : "r"((a)[0]), "r"((a)[1]), "r"((a)[2]), "r"((a)[3]), "r"(b0), "r"(b1))

__device__ __forceinline__ uint16_t bfu(__nv_bfloat16 h) { return __bfloat16_as_ushort(h); }

// split float4 into packed hi/lo bf16 (2x uint2)
__device__ __forceinline__ void split_pack(float4 v, uint2& hi, uint2& lo) {
    __nv_bfloat16 h0 = __float2bfloat16_rn(v.x);
    __nv_bfloat16 h1 = __float2bfloat16_rn(v.y);
    __nv_bfloat16 h2 = __float2bfloat16_rn(v.z);
    __nv_bfloat16 h3 = __float2bfloat16_rn(v.w);
    __nv_bfloat16 l0 = __float2bfloat16_rn(v.x - __bfloat162float(h0));
    __nv_bfloat16 l1 = __float2bfloat16_rn(v.y - __bfloat162float(h1));
    __nv_bfloat16 l2 = __float2bfloat16_rn(v.z - __bfloat162float(h2));
    __nv_bfloat16 l3 = __float2bfloat16_rn(v.w - __bfloat162float(h3));
    hi = make_uint2((uint32_t)bfu(h0) | ((uint32_t)bfu(h1) << 16),
                    (uint32_t)bfu(h2) | ((uint32_t)bfu(h3) << 16));
    lo = make_uint2((uint32_t)bfu(l0) | ((uint32_t)bfu(l1) << 16),
                    (uint32_t)bfu(l2) | ((uint32_t)bfu(l3) << 16));
}

// smem tile layout: 128 rows x 64 bf16 (128B/row), XOR swizzle on 16B groups
#define T_AHI 0
#define T_ALO 16384
#define T_BHI 32768
#define T_BLO 49152
#define SM_RB 65536                     // 128 ints (qkv rowbase)
#define SM_GEMM_TOTAL (65536 + 512)

// ---------------- prep kernels ----------------------------------------------
__global__ __launch_bounds__(256) void split_x_kernel(const float* __restrict__ x)
{
    int i = blockIdx.x * blockDim.x + threadIdx.x;   // one float4 per thread
    if (i < XSZ / 4) {
        float4 v = ((const float4*)x)[i];
        uint2 hi, lo;
        split_pack(v, hi, lo);
        ((uint2*)g_x_hi)[i] = hi;
        ((uint2*)g_x_lo)[i] = lo;
    }
}

__global__ __launch_bounds__(256) void split_w_kernel(const float* __restrict__ wqkv,
                                                      const float* __restrict__ wout)
{
    int i = blockIdx.x * blockDim.x + threadIdx.x;
    const int NQ4 = 768 * 256 / 4;
    const int NO4 = 256 * 256 / 4;
    if (i < NQ4) {
        float4 v = ((const float4*)wqkv)[i];
        uint2 hi, lo;
        split_pack(v, hi, lo);
        ((uint2*)g_wq_hi)[i] = hi;
        ((uint2*)g_wq_lo)[i] = lo;
    } else if (i < NQ4 + NO4) {
        int j = i - NQ4;
        float4 v = ((const float4*)wout)[j];
        uint2 hi, lo;
        split_pack(v, hi, lo);
        ((uint2*)g_wo_hi)[j] = hi;
        ((uint2*)g_wo_lo)[j] = lo;
    }
}

// ---------------------------------------------------------------------------
// Kernel 1: QKV GEMM via mma.sync bf16 3-pass (fragment-reuse form).
// grid (6, 3, 256), block 256. CTA tile 128x128, warp 32x64.
// ---------------------------------------------------------------------------
__global__ __launch_bounds__(256) void qkv_kernel()
{
    extern __shared__ char sm[];
    const uint32_t smb = smem_u32(sm);
    int* rb = (int*)(sm + SM_RB);

    const int bx = blockIdx.x;      // n-chunk (0..5)
    const int by = blockIdx.y;      // m-tile (0..2)
    const int w  = blockIdx.z;      // window
    const int tid = threadIdx.x;
    const int lane = tid & 31, wid = tid >> 5;
    const int wm = wid & 3, wn = wid >> 2;
    const int hx = w >> 4, wy = w & 15;

    if (tid < 128) {
        int n = by * 128 + tid;
        if (n < NTOK) {
            int l = n / 49; int rem = n - l * 49; int w1 = rem / 7; int w2 = rem - w1 * 7;
            rb[tid] = ((l * 256 + hx * 16 + wy) * 49 + w1 * 7 + w2) * 256;
        } else rb[tid] = -1;
    }
    __syncthreads();

    float acc[2][8][4];
    #pragma unroll
    for (int mt = 0; mt < 2; mt++)
        #pragma unroll
        for (int nt = 0; nt < 8; nt++)
            #pragma unroll
            for (int r = 0; r < 4; r++) acc[mt][nt][r] = 0.f;

    const int l7 = lane & 7;
    const uint32_t arow0 = (uint32_t)(wm * 32 + (lane & 15)) * 128;
    const int cgA = lane >> 4;
    const int g = lane >> 3;
    const uint32_t brow0 = (uint32_t)(wn * 64 + ((g & 2) << 2) + l7) * 128;
    const int cgB = g & 1;

    for (int chunk = 0; chunk < 4; chunk++) {
        // ---- stage 4 tiles (A_hi, A_lo, B_hi, B_lo), 16B units, swizzled ----
        #pragma unroll
        for (int i = 0; i < 16; i++) {
            int u = tid + i * 256;          // 0..4095
            int tile = u >> 10;
            int uu = u & 1023;
            int row = uu >> 3, kg = uu & 7;
            char* dst = sm + (tile << 14) + row * 128 + ((kg ^ (row & 7)) << 4);
            uint4 val = make_uint4(0u, 0u, 0u, 0u);
            if (tile < 2) {
                int base = rb[row];
                if (base >= 0) {
                    const __nv_bfloat16* src = (tile == 0 ? g_x_hi : g_x_lo)
                                               + base + chunk * 64 + kg * 8;
                    val = *(const uint4*)src;
                }
            } else {
                int nrow = bx * 128 + row;
                const __nv_bfloat16* src = (tile == 2 ? g_wq_hi : g_wq_lo)
                                           + nrow * 256 + chunk * 64 + kg * 8;
                val = *(const uint4*)src;
            }
            *(uint4*)dst = val;
        }
        __syncthreads();

        // ---- fragment-reuse MMA: 12 LDSM + 48 MMA per ks ----
        #pragma unroll
        for (int ks = 0; ks < 4; ks++) {
            uint32_t ah[2][4], al[2][4], bh[4][4], bl[4][4];
            uint32_t aswz = (uint32_t)((ks * 2 + cgA) ^ l7) << 4;
            LDSM4(ah[0], smb + T_AHI + arow0 + aswz);
            LDSM4(ah[1], smb + T_AHI + arow0 + 2048 + aswz);
            LDSM4(al[0], smb + T_ALO + arow0 + aswz);
            LDSM4(al[1], smb + T_ALO + arow0 + 2048 + aswz);
            uint32_t bswz = (uint32_t)((ks * 2 + cgB) ^ l7) << 4;
            #pragma unroll
            for (int p = 0; p < 4; p++) {
                LDSM4(bh[p], smb + T_BHI + brow0 + p * 2048 + bswz);
                LDSM4(bl[p], smb + T_BLO + brow0 + p * 2048 + bswz);
            }
            #pragma unroll
            for (int mt = 0; mt < 2; mt++)
                #pragma unroll
                for (int nt = 0; nt < 8; nt++) {
                    uint32_t h0 = bh[nt >> 1][(nt & 1) * 2], h1 = bh[nt >> 1][(nt & 1) * 2 + 1];
                    uint32_t lo0 = bl[nt >> 1][(nt & 1) * 2], lo1 = bl[nt >> 1][(nt & 1) * 2 + 1];
                    MMA16816(acc[mt][nt], ah[mt], h0, h1);
                    MMA16816(acc[mt][nt], al[mt], h0, h1);
                    MMA16816(acc[mt][nt], ah[mt], lo0, lo1);
                }
        }
        __syncthreads();
    }

    // ---- epilogue: scatter to g_q / g_k / g_v -------------------------------
    const int part = bx >> 1;                         // 0=q 1=k 2=v
    float* dstbuf = (part == 0) ? g_q : (part == 1) ? g_k : g_v;
    const float scale = (part == 0) ? QSCALE : 1.f;
    const int trow = lane >> 2;
    const int tcol2 = (lane & 3) * 2;

    #pragma unroll
    for (int mt = 0; mt < 2; mt++) {
        #pragma unroll
        for (int half = 0; half < 2; half++) {
            int r = by * 128 + wm * 32 + mt * 16 + trow + half * 8;
            if (r >= NTOK) continue;
            #pragma unroll
            for (int nt = 0; nt < 8; nt++) {
                int o = bx * 128 + wn * 64 + nt * 8 + tcol2;
                int h = (o & 255) >> 5, d = o & 31;
                float2 v = make_float2(acc[mt][nt][half * 2] * scale,
                                       acc[mt][nt][half * 2 + 1] * scale);
                *(float2*)(dstbuf + ((size_t)(w * 8 + h) * NTOK + r) * 32 + d) = v;
            }
        }
    }
}

// ---------------------------------------------------------------------------
// Kernel 2: attention per (window, head). 2048 blocks, 160 threads.
// EXACT round-2 form (fp32 epilogue to g_o) — the bf16 epilogue caused spills.
// ---------------------------------------------------------------------------
__global__ __launch_bounds__(160) void attn_kernel(const float* __restrict__ bias_table)
{
    extern __shared__ float smf[];
    float4* K4 = (float4*)smf;                        // 2352 float4
    float4* V4 = K4 + (NTOK * DH / 4);                // 2352 float4
    float*  bH = smf + 2 * NTOK * DH;                 // 1859 floats
    int*    cj = (int*)(bH + NBIAS);                  // 294 ints

    const int wh  = blockIdx.x;
    const int h   = wh & 7;
    const int w   = wh >> 3;
    const int tid = threadIdx.x;

    const float4* gK = (const float4*)(g_k + (size_t)wh * NTOK * DH);
    const float4* gV = (const float4*)(g_v + (size_t)wh * NTOK * DH);
    for (int i = tid; i < NTOK * DH / 4; i += 160) { K4[i] = gK[i]; V4[i] = gV[i]; }
    for (int i = tid; i < NBIAS; i += 160) bH[i] = bias_table[i * HEADS + h];
    for (int i = tid; i < NTOK; i += 160) {
        int l = i / 49, rem = i - l * 49, w1 = rem / 7, w2 = rem - w1 * 7;
        cj[i] = l * 169 + w1 * 13 + w2;
    }
    __syncthreads();

    const int r1 = tid;
    const int r2 = tid + 160;
    const bool v2 = (r2 < NTOK);

    float q1[32], q2[32];
    const float4* gQ = (const float4*)(g_q + (size_t)wh * NTOK * DH);
    #pragma unroll
    for (int kk = 0; kk < 8; kk++) {
        float4 a = gQ[r1 * 8 + kk];
        q1[4*kk+0] = a.x; q1[4*kk+1] = a.y; q1[4*kk+2] = a.z; q1[4*kk+3] = a.w;
        float4 b = v2 ? gQ[r2 * 8 + kk] : make_float4(0.f, 0.f, 0.f, 0.f);
        q2[4*kk+0] = b.x; q2[4*kk+1] = b.y; q2[4*kk+2] = b.z; q2[4*kk+3] = b.w;
    }

    float acc1[32], acc2[32];
    #pragma unroll
    for (int d = 0; d < 32; d++) { acc1[d] = 0.f; acc2[d] = 0.f; }
    float s1 = 0.f, s2 = 0.f;
    const int ci1 = cj[r1] + 929;
    const int ci2 = v2 ? (cj[r2] + 929) : 929;

    for (int j = 0; j < NTOK; j++) {
        int cjj = cj[j];
        float a0 = 0.f, a1 = 0.f, a2 = 0.f, a3 = 0.f;
        float e0 = 0.f, e1 = 0.f, e2 = 0.f, e3 = 0.f;
        #pragma unroll
        for (int kk = 0; kk < 8; kk++) {
            float4 kv = K4[j * 8 + kk];
            a0 += q1[4*kk+0] * kv.x;
            a1 += q1[4*kk+1] * kv.y;
            a2 += q1[4*kk+2] * kv.z;
            a3 += q1[4*kk+3] * kv.w;
            e0 += q2[4*kk+0] * kv.x;
            e1 += q2[4*kk+1] * kv.y;
            e2 += q2[4*kk+2] * kv.z;
            e3 += q2[4*kk+3] * kv.w;
        }
        float d1 = (a0 + a1) + (a2 + a3);
        float d2 = (e0 + e1) + (e2 + e3);
        float p1 = __expf(d1 + bH[ci1 - cjj]);
        float p2 = __expf(d2 + bH[ci2 - cjj]);
        s1 += p1; s2 += p2;
        #pragma unroll
        for (int kk = 0; kk < 8; kk++) {
            float4 vv = V4[j * 8 + kk];
            acc1[4*kk+0] += p1 * vv.x;  acc1[4*kk+1] += p1 * vv.y;
            acc1[4*kk+2] += p1 * vv.z;  acc1[4*kk+3] += p1 * vv.w;
            acc2[4*kk+0] += p2 * vv.x;  acc2[4*kk+1] += p2 * vv.y;
            acc2[4*kk+2] += p2 * vv.z;  acc2[4*kk+3] += p2 * vv.w;
        }
    }

    float inv1 = 1.f / s1;
    float4* dst1 = (float4*)(g_o + ((size_t)w * NTOK + r1) * DIM + h * DH);
    #pragma unroll
    for (int kk = 0; kk < 8; kk++)
        dst1[kk] = make_float4(acc1[4*kk+0]*inv1, acc1[4*kk+1]*inv1,
                               acc1[4*kk+2]*inv1, acc1[4*kk+3]*inv1);
    if (v2) {
        float inv2 = 1.f / s2;
        float4* dst2 = (float4*)(g_o + ((size_t)w * NTOK + r2) * DIM + h * DH);
        #pragma unroll
        for (int kk = 0; kk < 8; kk++)
            dst2[kk] = make_float4(acc2[4*kk+0]*inv2, acc2[4*kk+1]*inv2,
                                   acc2[4*kk+2]*inv2, acc2[4*kk+3]*inv2);
    }
}

// ---------------------------------------------------------------------------
// Kernel 3: output GEMM via mma.sync bf16 3-pass, staging splits fp32 g_o.
// grid (2, 3, 256), block 256.
// ---------------------------------------------------------------------------
__global__ __launch_bounds__(256) void out_kernel(float* __restrict__ out)
{
    extern __shared__ char sm[];
    const uint32_t smb = smem_u32(sm);

    const int bx = blockIdx.x;      // n-chunk (0..1)
    const int by = blockIdx.y;      // m-tile (0..2)
    const int w  = blockIdx.z;
    const int tid = threadIdx.x;
    const int lane = tid & 31, wid = tid >> 5;
    const int wm = wid & 3, wn = wid >> 2;
    const int hx = w >> 4, wy = w & 15;

    float acc[2][8][4];
    #pragma unroll
    for (int mt = 0; mt < 2; mt++)
        #pragma unroll
        for (int nt = 0; nt < 8; nt++)
            #pragma unroll
            for (int r = 0; r < 4; r++) acc[mt][nt][r] = 0.f;

    const int l7 = lane & 7;
    const uint32_t arow0 = (uint32_t)(wm * 32 + (lane & 15)) * 128;
    const int cgA = lane >> 4;
    const int g = lane >> 3;
    const uint32_t brow0 = (uint32_t)(wn * 64 + ((g & 2) << 2) + l7) * 128;
    const int cgB = g & 1;

    for (int chunk = 0; chunk < 4; chunk++) {
        // ---- A staging: load fp32 g_o, split inline to A_hi + A_lo ----
        #pragma unroll
        for (int i = 0; i < 4; i++) {
            int u = tid + i * 256;                 // 0..1023
            int row = u >> 3, kg = u & 7;
            uint32_t off = row * 128 + ((kg ^ (row & 7)) << 4);
            uint4 hi4 = make_uint4(0u, 0u, 0u, 0u);
            uint4 lo4 = make_uint4(0u, 0u, 0u, 0u);
            int tok = by * 128 + row;
            if (tok < NTOK) {
                const float* src = g_o + ((size_t)w * NTOK + tok) * DIM + chunk * 64 + kg * 8;
                float4 v0 = *(const float4*)src;
                float4 v1 = *(const float4*)(src + 4);
                uint2 h0, l0, h1, l1;
                split_pack(v0, h0, l0);
                split_pack(v1, h1, l1);
                hi4 = make_uint4(h0.x, h0.y, h1.x, h1.y);
                lo4 = make_uint4(l0.x, l0.y, l1.x, l1.y);
            }
            *(uint4*)(sm + T_AHI + off) = hi4;
            *(uint4*)(sm + T_ALO + off) = lo4;
        }
        // ---- B staging: pre-split weights ----
        #pragma unroll
        for (int i = 0; i < 8; i++) {
            int u = tid + i * 256;                 // 0..2047
            int half = u >> 10;
            int uu = u & 1023;
            int row = uu >> 3, kg = uu & 7;
            char* dst = sm + (half ? T_BLO : T_BHI) + row * 128 + ((kg ^ (row & 7)) << 4);
            int nrow = bx * 128 + row;
            const __nv_bfloat16* src = (half ? g_wo_lo : g_wo_hi)
                                       + nrow * 256 + chunk * 64 + kg * 8;
            *(uint4*)dst = *(const uint4*)src;
        }
        __syncthreads();

        #pragma unroll
        for (int ks = 0; ks < 4; ks++) {
            uint32_t ah[2][4], al[2][4], bh[4][4], bl[4][4];
            uint32_t aswz = (uint32_t)((ks * 2 + cgA) ^ l7) << 4;
            LDSM4(ah[0], smb + T_AHI + arow0 + aswz);
            LDSM4(ah[1], smb + T_AHI + arow0 + 2048 + aswz);
            LDSM4(al[0], smb + T_ALO + arow0 + aswz);
            LDSM4(al[1], smb + T_ALO + arow0 + 2048 + aswz);
            uint32_t bswz = (uint32_t)((ks * 2 + cgB) ^ l7) << 4;
            #pragma unroll
            for (int p = 0; p < 4; p++) {
                LDSM4(bh[p], smb + T_BHI + brow0 + p * 2048 + bswz);
                LDSM4(bl[p], smb + T_BLO + brow0 + p * 2048 + bswz);
            }
            #pragma unroll
            for (int mt = 0; mt < 2; mt++)
                #pragma unroll
                for (int nt = 0; nt < 8; nt++) {
                    uint32_t h0 = bh[nt >> 1][(nt & 1) * 2], h1 = bh[nt >> 1][(nt & 1) * 2 + 1];
                    uint32_t lo0 = bl[nt >> 1][(nt & 1) * 2], lo1 = bl[nt >> 1][(nt & 1) * 2 + 1];
                    MMA16816(acc[mt][nt], ah[mt], h0, h1);
                    MMA16816(acc[mt][nt], al[mt], h0, h1);
                    MMA16816(acc[mt][nt], ah[mt], lo0, lo1);
                }
        }
        __syncthreads();
    }

    const int trow = lane >> 2;
    const int tcol2 = (lane & 3) * 2;
    #pragma unroll
    for (int mt = 0; mt < 2; mt++) {
        #pragma unroll
        for (int half = 0; half < 2; half++) {
            int r = by * 128 + wm * 32 + mt * 16 + trow + half * 8;
            if (r >= NTOK) continue;
            int l = r / 49; int rem = r - l * 49; int w1 = rem / 7; int w2 = rem - w1 * 7;
            int ob = ((l * 256 + hx * 16 + wy) * 49 + w1 * 7 + w2) * 256;
            #pragma unroll
            for (int nt = 0; nt < 8; nt++) {
                int o = bx * 128 + wn * 64 + nt * 8 + tcol2;
                *(float2*)(out + ob + o) = make_float2(acc[mt][nt][half * 2],
                                                       acc[mt][nt][half * 2 + 1]);
            }
        }
    }
}

// ---------------------------------------------------------------------------
extern "C" void kernel_launch(void* const* d_in, const int* in_sizes, int n_in,
                              void* d_out, int out_size)
{
    const float* x    = (const float*)d_in[0];   // [1,6,16,16,7,7,256]
    const float* wqkv = (const float*)d_in[1];   // [768,256]
    const float* wout = (const float*)d_in[2];   // [256,256]
    const float* bias = (const float*)d_in[3];   // [1859,8]
    float* out = (float*)d_out;

    const int attn_smem = (2 * NTOK * DH + NBIAS + NTOK) * (int)sizeof(float);
    cudaFuncSetAttribute(attn_kernel, cudaFuncAttributeMaxDynamicSharedMemorySize, attn_smem);
    cudaFuncSetAttribute(qkv_kernel, cudaFuncAttributeMaxDynamicSharedMemorySize, SM_GEMM_TOTAL);
    cudaFuncSetAttribute(out_kernel, cudaFuncAttributeMaxDynamicSharedMemorySize, SM_GEMM_TOTAL);

    split_x_kernel<<<(XSZ / 4 + 255) / 256, 256>>>(x);
    split_w_kernel<<<(768 * 256 / 4 + 256 * 256 / 4 + 255) / 256, 256>>>(wqkv, wout);
    qkv_kernel<<<dim3(6, 3, 256), 256, SM_GEMM_TOTAL>>>();
    attn_kernel<<<2048, 160, attn_smem>>>(bias);
    out_kernel<<<dim3(2, 3, 256), 256, SM_GEMM_TOTAL>>>(out);
}

// round 6
// speedup vs baseline: 1.6548x; 1.0846x over previous
#include <cuda_runtime.h>
#include <cuda_bf16.h>
#include <cstdint>

#define NTOK   294
#define NTOKP  304
#define HEADS  8
#define DH     32
#define DIM    256
#define NWIN   256
#define NBIAS  1859
#define QSCALE 0.17677669529663687f  // 32^-0.5
#define XSZ    (6 * 16 * 16 * 7 * 7 * 256)   // 19267584

// ---------------- scratch (allocation-free: __device__ globals) -------------
__device__ float g_o[NWIN * NTOK * DIM];
__device__ __nv_bfloat16 g_x_hi[XSZ];
__device__ __nv_bfloat16 g_x_lo[XSZ];
__device__ __nv_bfloat16 g_wq_hi[768 * 256];
__device__ __nv_bfloat16 g_wq_lo[768 * 256];
__device__ __nv_bfloat16 g_wo_hi[256 * 256];
__device__ __nv_bfloat16 g_wo_lo[256 * 256];
// q/k/v as bf16 hi/lo, layout [wh][NTOK][32]
__device__ __nv_bfloat16 g_qh[NWIN * HEADS * NTOK * DH];
__device__ __nv_bfloat16 g_ql[NWIN * HEADS * NTOK * DH];
__device__ __nv_bfloat16 g_kh[NWIN * HEADS * NTOK * DH];
__device__ __nv_bfloat16 g_kl[NWIN * HEADS * NTOK * DH];
__device__ __nv_bfloat16 g_vh[NWIN * HEADS * NTOK * DH];
__device__ __nv_bfloat16 g_vl[NWIN * HEADS * NTOK * DH];

// ---------------- helpers ---------------------------------------------------
__device__ __forceinline__ uint32_t smem_u32(const void* p) {
    uint32_t a;
    asm("{ .reg .u64 t; cvta.to.shared.u64 t, %1; cvt.u32.u64 %0, t; }" : "=r"(a) : "l"(p));
    return a;
}

#define LDSM4(r, a) \
    asm volatile("ldmatrix.sync.aligned.m8n8.x4.shared.b16 {%0,%1,%2,%3}, [%4];" \
        : "=r"((r)[0]), "=r"((r)[1]), "=r"((r)[2]), "=r"((r)[3]) : "r"(a))
#define LDSM4T(r, a) \
    asm volatile("ldmatrix.sync.aligned.m8n8.x4.trans.shared.b16 {%0,%1,%2,%3}, [%4];" \
        : "=r"((r)[0]), "=r"((r)[1]), "=r"((r)[2]), "=r"((r)[3]) : "r"(a))

#define MMA16816(d, a, b0, b1) \
    asm volatile("mma.sync.aligned.m16n8k16.row.col.f32.bf16.bf16.f32 " \
        "{%0,%1,%2,%3}, {%4,%5,%6,%7}, {%8,%9}, {%0,%1,%2,%3};" \
        : "+f"((d)[0]), "+f"((d)[1]), "+f"((d)[2]), "+f"((d)[3]) \
        : "r"((a)[0]), "r"((a)[1]), "r"((a)[2]), "r"((a)[3]), "r"(b0), "r"(b1))

__device__ __forceinline__ uint16_t bfu(__nv_bfloat16 h) { return __bfloat16_as_ushort(h); }

__device__ __forceinline__ void pack_hl(float a, float b, uint32_t& hi, uint32_t& lo) {
    __nv_bfloat16 ha = __float2bfloat16_rn(a), hb = __float2bfloat16_rn(b);
    __nv_bfloat16 la = __float2bfloat16_rn(a - __bfloat162float(ha));
    __nv_bfloat16 lb = __float2bfloat16_rn(b - __bfloat162float(hb));
    hi = (uint32_t)bfu(ha) | ((uint32_t)bfu(hb) << 16);
    lo = (uint32_t)bfu(la) | ((uint32_t)bfu(lb) << 16);
}

// split float4 into packed hi/lo bf16 (2x uint2)
__device__ __forceinline__ void split_pack(float4 v, uint2& hi, uint2& lo) {
    pack_hl(v.x, v.y, hi.x, lo.x);
    pack_hl(v.z, v.w, hi.y, lo.y);
}

// GEMM smem tile layout
#define T_AHI 0
#define T_ALO 16384
#define T_BHI 32768
#define T_BLO 49152
#define SM_RB 65536
#define SM_GEMM_TOTAL (65536 + 512)

// attention smem layout (bytes); rows padded to 40 bf16 = 80B
#define A_KH 0
#define A_KL 24320
#define A_VH 48640
#define A_VL 72960
#define A_BH 97280                      // 1859 floats
#define A_CJ 104716                     // 304 ints
#define ATTN_SMEM 105936

// ---------------- prep kernels ----------------------------------------------
__global__ __launch_bounds__(256) void split_x_kernel(const float* __restrict__ x)
{
    int i = blockIdx.x * blockDim.x + threadIdx.x;
    if (i < XSZ / 4) {
        float4 v = ((const float4*)x)[i];
        uint2 hi, lo;
        split_pack(v, hi, lo);
        ((uint2*)g_x_hi)[i] = hi;
        ((uint2*)g_x_lo)[i] = lo;
    }
}

__global__ __launch_bounds__(256) void split_w_kernel(const float* __restrict__ wqkv,
                                                      const float* __restrict__ wout)
{
    int i = blockIdx.x * blockDim.x + threadIdx.x;
    const int NQ4 = 768 * 256 / 4;
    const int NO4 = 256 * 256 / 4;
    if (i < NQ4) {
        float4 v = ((const float4*)wqkv)[i];
        uint2 hi, lo;
        split_pack(v, hi, lo);
        ((uint2*)g_wq_hi)[i] = hi;
        ((uint2*)g_wq_lo)[i] = lo;
    } else if (i < NQ4 + NO4) {
        int j = i - NQ4;
        float4 v = ((const float4*)wout)[j];
        uint2 hi, lo;
        split_pack(v, hi, lo);
        ((uint2*)g_wo_hi)[j] = hi;
        ((uint2*)g_wo_lo)[j] = lo;
    }
}

// ---------------------------------------------------------------------------
// Kernel 1: QKV GEMM via mma.sync bf16 3-pass. Epilogue emits bf16 hi/lo.
// grid (6, 3, 256), block 256.
// ---------------------------------------------------------------------------
__global__ __launch_bounds__(256) void qkv_kernel()
{
    extern __shared__ char sm[];
    const uint32_t smb = smem_u32(sm);
    int* rb = (int*)(sm + SM_RB);

    const int bx = blockIdx.x;
    const int by = blockIdx.y;
    const int w  = blockIdx.z;
    const int tid = threadIdx.x;
    const int lane = tid & 31, wid = tid >> 5;
    const int wm = wid & 3, wn = wid >> 2;
    const int hx = w >> 4, wy = w & 15;

    if (tid < 128) {
        int n = by * 128 + tid;
        if (n < NTOK) {
            int l = n / 49; int rem = n - l * 49; int w1 = rem / 7; int w2 = rem - w1 * 7;
            rb[tid] = ((l * 256 + hx * 16 + wy) * 49 + w1 * 7 + w2) * 256;
        } else rb[tid] = -1;
    }
    __syncthreads();

    float acc[2][8][4];
    #pragma unroll
    for (int mt = 0; mt < 2; mt++)
        #pragma unroll
        for (int nt = 0; nt < 8; nt++)
            #pragma unroll
            for (int r = 0; r < 4; r++) acc[mt][nt][r] = 0.f;

    const int l7 = lane & 7;
    const uint32_t arow0 = (uint32_t)(wm * 32 + (lane & 15)) * 128;
    const int cgA = lane >> 4;
    const int g = lane >> 3;
    const uint32_t brow0 = (uint32_t)(wn * 64 + ((g & 2) << 2) + l7) * 128;
    const int cgB = g & 1;

    for (int chunk = 0; chunk < 4; chunk++) {
        #pragma unroll
        for (int i = 0; i < 16; i++) {
            int u = tid + i * 256;
            int tile = u >> 10;
            int uu = u & 1023;
            int row = uu >> 3, kg = uu & 7;
            char* dst = sm + (tile << 14) + row * 128 + ((kg ^ (row & 7)) << 4);
            uint4 val = make_uint4(0u, 0u, 0u, 0u);
            if (tile < 2) {
                int base = rb[row];
                if (base >= 0) {
                    const __nv_bfloat16* src = (tile == 0 ? g_x_hi : g_x_lo)
                                               + base + chunk * 64 + kg * 8;
                    val = *(const uint4*)src;
                }
            } else {
                int nrow = bx * 128 + row;
                const __nv_bfloat16* src = (tile == 2 ? g_wq_hi : g_wq_lo)
                                           + nrow * 256 + chunk * 64 + kg * 8;
                val = *(const uint4*)src;
            }
            *(uint4*)dst = val;
        }
        __syncthreads();

        #pragma unroll
        for (int ks = 0; ks < 4; ks++) {
            uint32_t ah[2][4], al[2][4], bh[4][4], bl[4][4];
            uint32_t aswz = (uint32_t)((ks * 2 + cgA) ^ l7) << 4;
            LDSM4(ah[0], smb + T_AHI + arow0 + aswz);
            LDSM4(ah[1], smb + T_AHI + arow0 + 2048 + aswz);
            LDSM4(al[0], smb + T_ALO + arow0 + aswz);
            LDSM4(al[1], smb + T_ALO + arow0 + 2048 + aswz);
            uint32_t bswz = (uint32_t)((ks * 2 + cgB) ^ l7) << 4;
            #pragma unroll
            for (int p = 0; p < 4; p++) {
                LDSM4(bh[p], smb + T_BHI + brow0 + p * 2048 + bswz);
                LDSM4(bl[p], smb + T_BLO + brow0 + p * 2048 + bswz);
            }
            #pragma unroll
            for (int mt = 0; mt < 2; mt++)
                #pragma unroll
                for (int nt = 0; nt < 8; nt++) {
                    uint32_t h0 = bh[nt >> 1][(nt & 1) * 2], h1 = bh[nt >> 1][(nt & 1) * 2 + 1];
                    uint32_t lo0 = bl[nt >> 1][(nt & 1) * 2], lo1 = bl[nt >> 1][(nt & 1) * 2 + 1];
                    MMA16816(acc[mt][nt], ah[mt], h0, h1);
                    MMA16816(acc[mt][nt], al[mt], h0, h1);
                    MMA16816(acc[mt][nt], ah[mt], lo0, lo1);
                }
        }
        __syncthreads();
    }

    // ---- epilogue: split + scatter to bf16 hi/lo q/k/v ---------------------
    const int part = bx >> 1;
    __nv_bfloat16* dh_ = (part == 0) ? g_qh : (part == 1) ? g_kh : g_vh;
    __nv_bfloat16* dl_ = (part == 0) ? g_ql : (part == 1) ? g_kl : g_vl;
    const float scale = (part == 0) ? QSCALE : 1.f;
    const int trow = lane >> 2;
    const int tcol2 = (lane & 3) * 2;

    #pragma unroll
    for (int mt = 0; mt < 2; mt++) {
        #pragma unroll
        for (int half = 0; half < 2; half++) {
            int r = by * 128 + wm * 32 + mt * 16 + trow + half * 8;
            if (r >= NTOK) continue;
            #pragma unroll
            for (int nt = 0; nt < 8; nt++) {
                int o = bx * 128 + wn * 64 + nt * 8 + tcol2;
                int hh = (o & 255) >> 5, d = o & 31;
                uint32_t hip, lop;
                pack_hl(acc[mt][nt][half * 2] * scale,
                        acc[mt][nt][half * 2 + 1] * scale, hip, lop);
                size_t off = ((size_t)(w * 8 + hh) * NTOK + r) * 32 + d;
                *(uint32_t*)(dh_ + off) = hip;
                *(uint32_t*)(dl_ + off) = lop;
            }
        }
    }
}

// ---------------------------------------------------------------------------
// Kernel 2: tensor-core attention. One CTA per (window, head), 320 threads.
// Warp wm owns rows 32*wm..32*wm+31 (2 m16 tiles). K/V hi/lo in smem.
// ---------------------------------------------------------------------------
__global__ __launch_bounds__(320) void attn_kernel(const float* __restrict__ bias_table)
{
    extern __shared__ char sm[];
    const uint32_t smb = smem_u32(sm);
    float* bH  = (float*)(sm + A_BH);
    int*   cjs = (int*)(sm + A_CJ);

    const int wh = blockIdx.x;
    const int h  = wh & 7;
    const int w  = wh >> 3;
    const int tid = threadIdx.x;
    const int lane = tid & 31, wm = tid >> 5;
    const int t4 = lane & 3, g = lane >> 2;
    const size_t base = (size_t)wh * NTOK * DH;

    // ---- stage K/V hi/lo into smem (80B row stride, pad rows zeroed) ------
    {
        const __nv_bfloat16* srcs[4] = {g_kh + base, g_kl + base, g_vh + base, g_vl + base};
        const uint32_t dsts[4] = {A_KH, A_KL, A_VH, A_VL};
        for (int idx = tid; idx < 4 * NTOKP * 4; idx += 320) {
            int arr = idx / (NTOKP * 4);
            int rem = idx - arr * (NTOKP * 4);
            int row = rem >> 2, seg = rem & 3;
            uint4 val = make_uint4(0u, 0u, 0u, 0u);
            if (row < NTOK) val = *(const uint4*)(srcs[arr] + row * 32 + seg * 8);
            *(uint4*)(sm + dsts[arr] + row * 80 + seg * 16) = val;
        }
        for (int i = tid; i < NBIAS; i += 320) bH[i] = bias_table[i * HEADS + h];
        for (int i = tid; i < NTOKP; i += 320) {
            if (i < NTOK) {
                int l = i / 49, rem = i - l * 49, w1 = rem / 7, w2 = rem - w1 * 7;
                cjs[i] = l * 169 + w1 * 13 + w2;
            } else cjs[i] = 0;
        }
    }

    // ---- load Q fragments directly from gmem (bf16 hi/lo) -----------------
    const int R = wm * 32;
    uint32_t aQh[2][2][4], aQl[2][2][4];
    #pragma unroll
    for (int mt = 0; mt < 2; mt++) {
        int r0 = R + mt * 16 + g, r1 = r0 + 8;
        #pragma unroll
        for (int kh = 0; kh < 2; kh++) {
            int c0 = kh * 16 + 2 * t4, c1 = c0 + 8;
            aQh[mt][kh][0] = (r0 < NTOK) ? *(const uint32_t*)(g_qh + base + r0 * 32 + c0) : 0u;
            aQh[mt][kh][1] = (r1 < NTOK) ? *(const uint32_t*)(g_qh + base + r1 * 32 + c0) : 0u;
            aQh[mt][kh][2] = (r0 < NTOK) ? *(const uint32_t*)(g_qh + base + r0 * 32 + c1) : 0u;
            aQh[mt][kh][3] = (r1 < NTOK) ? *(const uint32_t*)(g_qh + base + r1 * 32 + c1) : 0u;
            aQl[mt][kh][0] = (r0 < NTOK) ? *(const uint32_t*)(g_ql + base + r0 * 32 + c0) : 0u;
            aQl[mt][kh][1] = (r1 < NTOK) ? *(const uint32_t*)(g_ql + base + r1 * 32 + c0) : 0u;
            aQl[mt][kh][2] = (r0 < NTOK) ? *(const uint32_t*)(g_ql + base + r0 * 32 + c1) : 0u;
            aQl[mt][kh][3] = (r1 < NTOK) ? *(const uint32_t*)(g_ql + base + r1 * 32 + c1) : 0u;
        }
    }
    __syncthreads();

    // row-position codes (+929) for bias; pad rows use row 293's (harmless)
    int ci[2][2];
    #pragma unroll
    for (int mt = 0; mt < 2; mt++) {
        int r0 = R + mt * 16 + g, r1 = r0 + 8;
        ci[mt][0] = cjs[r0 < NTOK ? r0 : NTOK - 1] + 929;
        ci[mt][1] = cjs[r1 < NTOK ? r1 : NTOK - 1] + 929;
    }

    float O[2][4][4];
    #pragma unroll
    for (int mt = 0; mt < 2; mt++)
        #pragma unroll
        for (int dn = 0; dn < 4; dn++)
            #pragma unroll
            for (int e = 0; e < 4; e++) O[mt][dn][e] = 0.f;
    float rs[2][2] = {{0.f, 0.f}, {0.f, 0.f}};

    // per-lane ldmatrix address shape (row/col select within a 16x16 tile)
    const int lrow = ((lane & 8) ? 8 : 0) + (lane & 7);
    const int lcol = (lane & 16) ? 8 : 0;

    for (int j0 = 0; j0 < NTOKP; j0 += 16) {
        // ---- K b-fragments ------------------------------------------------
        uint32_t bkh[2][2][2], bkl[2][2][2];    // [jn][kh][b0/b1]
        #pragma unroll
        for (int kh = 0; kh < 2; kh++) {
            uint32_t addr = (uint32_t)((j0 + lrow) * 80 + (kh * 16 + lcol) * 2);
            uint32_t t[4];
            LDSM4(t, smb + A_KH + addr);
            bkh[0][kh][0] = t[0]; bkh[0][kh][1] = t[2];
            bkh[1][kh][0] = t[1]; bkh[1][kh][1] = t[3];
            LDSM4(t, smb + A_KL + addr);
            bkl[0][kh][0] = t[0]; bkl[0][kh][1] = t[2];
            bkl[1][kh][0] = t[1]; bkl[1][kh][1] = t[3];
        }

        // ---- S = Q K^T (3-pass hi/lo) ------------------------------------
        float S[2][2][4];
        #pragma unroll
        for (int mt = 0; mt < 2; mt++)
            #pragma unroll
            for (int jn = 0; jn < 2; jn++) {
                #pragma unroll
                for (int e = 0; e < 4; e++) S[mt][jn][e] = 0.f;
                #pragma unroll
                for (int kh = 0; kh < 2; kh++) {
                    MMA16816(S[mt][jn], aQh[mt][kh], bkh[jn][kh][0], bkh[jn][kh][1]);
                    MMA16816(S[mt][jn], aQl[mt][kh], bkh[jn][kh][0], bkh[jn][kh][1]);
                    MMA16816(S[mt][jn], aQh[mt][kh], bkl[jn][kh][0], bkl[jn][kh][1]);
                }
            }

        // ---- P = exp(S + bias), masked; pack to bf16 hi/lo A-frags -------
        int   jb[2];
        int   cjv[2][2];
        bool  va[2][2];
        #pragma unroll
        for (int jn = 0; jn < 2; jn++) {
            jb[jn] = j0 + 8 * jn + 2 * t4;
            cjv[jn][0] = cjs[jb[jn]];
            cjv[jn][1] = cjs[jb[jn] + 1];
            va[jn][0] = (jb[jn] < NTOK);
            va[jn][1] = (jb[jn] + 1 < NTOK);
        }
        uint32_t aPh[2][4], aPl[2][4];
        #pragma unroll
        for (int mt = 0; mt < 2; mt++) {
            float p[2][4];
            #pragma unroll
            for (int jn = 0; jn < 2; jn++) {
                p[jn][0] = va[jn][0] ? __expf(S[mt][jn][0] + bH[ci[mt][0] - cjv[jn][0]]) : 0.f;
                p[jn][1] = va[jn][1] ? __expf(S[mt][jn][1] + bH[ci[mt][0] - cjv[jn][1]]) : 0.f;
                p[jn][2] = va[jn][0] ? __expf(S[mt][jn][2] + bH[ci[mt][1] - cjv[jn][0]]) : 0.f;
                p[jn][3] = va[jn][1] ? __expf(S[mt][jn][3] + bH[ci[mt][1] - cjv[jn][1]]) : 0.f;
                rs[mt][0] += p[jn][0] + p[jn][1];
                rs[mt][1] += p[jn][2] + p[jn][3];
            }
            pack_hl(p[0][0], p[0][1], aPh[mt][0], aPl[mt][0]);
            pack_hl(p[0][2], p[0][3], aPh[mt][1], aPl[mt][1]);
            pack_hl(p[1][0], p[1][1], aPh[mt][2], aPl[mt][2]);
            pack_hl(p[1][2], p[1][3], aPh[mt][3], aPl[mt][3]);
        }

        // ---- V b-fragments (trans) ---------------------------------------
        uint32_t bvh[4][2], bvl[4][2];          // [dn][b0/b1]
        #pragma unroll
        for (int dh2 = 0; dh2 < 2; dh2++) {
            uint32_t addr = (uint32_t)((j0 + lrow) * 80 + (dh2 * 16 + lcol) * 2);
            uint32_t t[4];
            LDSM4T(t, smb + A_VH + addr);
            bvh[dh2 * 2][0] = t[0]; bvh[dh2 * 2][1] = t[1];
            bvh[dh2 * 2 + 1][0] = t[2]; bvh[dh2 * 2 + 1][1] = t[3];
            LDSM4T(t, smb + A_VL + addr);
            bvl[dh2 * 2][0] = t[0]; bvl[dh2 * 2][1] = t[1];
            bvl[dh2 * 2 + 1][0] = t[2]; bvl[dh2 * 2 + 1][1] = t[3];
        }

        // ---- O += P V (3-pass hi/lo) -------------------------------------
        #pragma unroll
        for (int mt = 0; mt < 2; mt++)
            #pragma unroll
            for (int dn = 0; dn < 4; dn++) {
                MMA16816(O[mt][dn], aPh[mt], bvh[dn][0], bvh[dn][1]);
                MMA16816(O[mt][dn], aPl[mt], bvh[dn][0], bvh[dn][1]);
                MMA16816(O[mt][dn], aPh[mt], bvl[dn][0], bvl[dn][1]);
            }
    }

    // ---- normalize + write g_o (fp32) -------------------------------------
    #pragma unroll
    for (int mt = 0; mt < 2; mt++)
        #pragma unroll
        for (int h2 = 0; h2 < 2; h2++) {
            float v = rs[mt][h2];
            v += __shfl_xor_sync(0xFFFFFFFFu, v, 1);
            v += __shfl_xor_sync(0xFFFFFFFFu, v, 2);
            rs[mt][h2] = 1.f / v;
        }
    #pragma unroll
    for (int mt = 0; mt < 2; mt++)
        #pragma unroll
        for (int h2 = 0; h2 < 2; h2++) {
            int row = R + mt * 16 + g + 8 * h2;
            if (row >= NTOK) continue;
            float inv = rs[mt][h2];
            float* dst = g_o + ((size_t)w * NTOK + row) * DIM + h * DH;
            #pragma unroll
            for (int dn = 0; dn < 4; dn++) {
                int col = dn * 8 + 2 * t4;
                *(float2*)(dst + col) = make_float2(O[mt][dn][h2 * 2] * inv,
                                                    O[mt][dn][h2 * 2 + 1] * inv);
            }
        }
}

// ---------------------------------------------------------------------------
// Kernel 3: output GEMM via mma.sync bf16 3-pass, staging splits fp32 g_o.
// grid (2, 3, 256), block 256. (unchanged from round 5)
// ---------------------------------------------------------------------------
__global__ __launch_bounds__(256) void out_kernel(float* __restrict__ out)
{
    extern __shared__ char sm[];
    const uint32_t smb = smem_u32(sm);

    const int bx = blockIdx.x;
    const int by = blockIdx.y;
    const int w  = blockIdx.z;
    const int tid = threadIdx.x;
    const int lane = tid & 31, wid = tid >> 5;
    const int wm = wid & 3, wn = wid >> 2;
    const int hx = w >> 4, wy = w & 15;

    float acc[2][8][4];
    #pragma unroll
    for (int mt = 0; mt < 2; mt++)
        #pragma unroll
        for (int nt = 0; nt < 8; nt++)
            #pragma unroll
            for (int r = 0; r < 4; r++) acc[mt][nt][r] = 0.f;

    const int l7 = lane & 7;
    const uint32_t arow0 = (uint32_t)(wm * 32 + (lane & 15)) * 128;
    const int cgA = lane >> 4;
    const int g = lane >> 3;
    const uint32_t brow0 = (uint32_t)(wn * 64 + ((g & 2) << 2) + l7) * 128;
    const int cgB = g & 1;

    for (int chunk = 0; chunk < 4; chunk++) {
        #pragma unroll
        for (int i = 0; i < 4; i++) {
            int u = tid + i * 256;
            int row = u >> 3, kg = u & 7;
            uint32_t off = row * 128 + ((kg ^ (row & 7)) << 4);
            uint4 hi4 = make_uint4(0u, 0u, 0u, 0u);
            uint4 lo4 = make_uint4(0u, 0u, 0u, 0u);
            int tok = by * 128 + row;
            if (tok < NTOK) {
                const float* src = g_o + ((size_t)w * NTOK + tok) * DIM + chunk * 64 + kg * 8;
                float4 v0 = *(const float4*)src;
                float4 v1 = *(const float4*)(src + 4);
                uint2 h0, l0, h1, l1;
                split_pack(v0, h0, l0);
                split_pack(v1, h1, l1);
                hi4 = make_uint4(h0.x, h0.y, h1.x, h1.y);
                lo4 = make_uint4(l0.x, l0.y, l1.x, l1.y);
            }
            *(uint4*)(sm + T_AHI + off) = hi4;
            *(uint4*)(sm + T_ALO + off) = lo4;
        }
        #pragma unroll
        for (int i = 0; i < 8; i++) {
            int u = tid + i * 256;
            int half = u >> 10;
            int uu = u & 1023;
            int row = uu >> 3, kg = uu & 7;
            char* dst = sm + (half ? T_BLO : T_BHI) + row * 128 + ((kg ^ (row & 7)) << 4);
            int nrow = bx * 128 + row;
            const __nv_bfloat16* src = (half ? g_wo_lo : g_wo_hi)
                                       + nrow * 256 + chunk * 64 + kg * 8;
            *(uint4*)dst = *(const uint4*)src;
        }
        __syncthreads();

        #pragma unroll
        for (int ks = 0; ks < 4; ks++) {
            uint32_t ah[2][4], al[2][4], bh[4][4], bl[4][4];
            uint32_t aswz = (uint32_t)((ks * 2 + cgA) ^ l7) << 4;
            LDSM4(ah[0], smb + T_AHI + arow0 + aswz);
            LDSM4(ah[1], smb + T_AHI + arow0 + 2048 + aswz);
            LDSM4(al[0], smb + T_ALO + arow0 + aswz);
            LDSM4(al[1], smb + T_ALO + arow0 + 2048 + aswz);
            uint32_t bswz = (uint32_t)((ks * 2 + cgB) ^ l7) << 4;
            #pragma unroll
            for (int p = 0; p < 4; p++) {
                LDSM4(bh[p], smb + T_BHI + brow0 + p * 2048 + bswz);
                LDSM4(bl[p], smb + T_BLO + brow0 + p * 2048 + bswz);
            }
            #pragma unroll
            for (int mt = 0; mt < 2; mt++)
                #pragma unroll
                for (int nt = 0; nt < 8; nt++) {
                    uint32_t h0 = bh[nt >> 1][(nt & 1) * 2], h1 = bh[nt >> 1][(nt & 1) * 2 + 1];
                    uint32_t lo0 = bl[nt >> 1][(nt & 1) * 2], lo1 = bl[nt >> 1][(nt & 1) * 2 + 1];
                    MMA16816(acc[mt][nt], ah[mt], h0, h1);
                    MMA16816(acc[mt][nt], al[mt], h0, h1);
                    MMA16816(acc[mt][nt], ah[mt], lo0, lo1);
                }
        }
        __syncthreads();
    }

    const int trow = lane >> 2;
    const int tcol2 = (lane & 3) * 2;
    #pragma unroll
    for (int mt = 0; mt < 2; mt++) {
        #pragma unroll
        for (int half = 0; half < 2; half++) {
            int r = by * 128 + wm * 32 + mt * 16 + trow + half * 8;
            if (r >= NTOK) continue;
            int l = r / 49; int rem = r - l * 49; int w1 = rem / 7; int w2 = rem - w1 * 7;
            int ob = ((l * 256 + hx * 16 + wy) * 49 + w1 * 7 + w2) * 256;
            #pragma unroll
            for (int nt = 0; nt < 8; nt++) {
                int o = bx * 128 + wn * 64 + nt * 8 + tcol2;
                *(float2*)(out + ob + o) = make_float2(acc[mt][nt][half * 2],
                                                       acc[mt][nt][half * 2 + 1]);
            }
        }
    }
}

// ---------------------------------------------------------------------------
extern "C" void kernel_launch(void* const* d_in, const int* in_sizes, int n_in,
                              void* d_out, int out_size)
{
    const float* x    = (const float*)d_in[0];
    const float* wqkv = (const float*)d_in[1];
    const float* wout = (const float*)d_in[2];
    const float* bias = (const float*)d_in[3];
    float* out = (float*)d_out;

    cudaFuncSetAttribute(attn_kernel, cudaFuncAttributeMaxDynamicSharedMemorySize, ATTN_SMEM);
    cudaFuncSetAttribute(qkv_kernel, cudaFuncAttributeMaxDynamicSharedMemorySize, SM_GEMM_TOTAL);
    cudaFuncSetAttribute(out_kernel, cudaFuncAttributeMaxDynamicSharedMemorySize, SM_GEMM_TOTAL);

    split_x_kernel<<<(XSZ / 4 + 255) / 256, 256>>>(x);
    split_w_kernel<<<(768 * 256 / 4 + 256 * 256 / 4 + 255) / 256, 256>>>(wqkv, wout);
    qkv_kernel<<<dim3(6, 3, 256), 256, SM_GEMM_TOTAL>>>();
    attn_kernel<<<2048, 320, ATTN_SMEM>>>(bias);
    out_kernel<<<dim3(2, 3, 256), 256, SM_GEMM_TOTAL>>>(out);
}

// round 7
// speedup vs baseline: 1.8215x; 1.1007x over previous
#include <cuda_runtime.h>
#include <cuda_bf16.h>
#include <cstdint>

#define NTOK   294
#define NTOKP  304
#define HEADS  8
#define DH     32
#define DIM    256
#define NWIN   256
#define NBIAS  1859
#define QSCALE 0.17677669529663687f  // 32^-0.5
#define XSZ    (6 * 16 * 16 * 7 * 7 * 256)   // 19267584

// ---------------- scratch (allocation-free: __device__ globals) -------------
__device__ float g_o[NWIN * NTOK * DIM];
__device__ __nv_bfloat16 g_x_hi[XSZ];
__device__ __nv_bfloat16 g_x_lo[XSZ];
__device__ __nv_bfloat16 g_wq_hi[768 * 256];
__device__ __nv_bfloat16 g_wq_lo[768 * 256];
__device__ __nv_bfloat16 g_wo_hi[256 * 256];
__device__ __nv_bfloat16 g_wo_lo[256 * 256];
// q/k/v as bf16 hi/lo, layout [wh][NTOK][32]
__device__ __nv_bfloat16 g_qh[NWIN * HEADS * NTOK * DH];
__device__ __nv_bfloat16 g_ql[NWIN * HEADS * NTOK * DH];
__device__ __nv_bfloat16 g_kh[NWIN * HEADS * NTOK * DH];
__device__ __nv_bfloat16 g_kl[NWIN * HEADS * NTOK * DH];
__device__ __nv_bfloat16 g_vh[NWIN * HEADS * NTOK * DH];
__device__ __nv_bfloat16 g_vl[NWIN * HEADS * NTOK * DH];

// ---------------- helpers ---------------------------------------------------
__device__ __forceinline__ uint32_t smem_u32(const void* p) {
    uint32_t a;
    asm("{ .reg .u64 t; cvta.to.shared.u64 t, %1; cvt.u32.u64 %0, t; }" : "=r"(a) : "l"(p));
    return a;
}

#define LDSM4(r, a) \
    asm volatile("ldmatrix.sync.aligned.m8n8.x4.shared.b16 {%0,%1,%2,%3}, [%4];" \
        : "=r"((r)[0]), "=r"((r)[1]), "=r"((r)[2]), "=r"((r)[3]) : "r"(a))
#define LDSM4T(r, a) \
    asm volatile("ldmatrix.sync.aligned.m8n8.x4.trans.shared.b16 {%0,%1,%2,%3}, [%4];" \
        : "=r"((r)[0]), "=r"((r)[1]), "=r"((r)[2]), "=r"((r)[3]) : "r"(a))

#define MMA16816(d, a, b0, b1) \
    asm volatile("mma.sync.aligned.m16n8k16.row.col.f32.bf16.bf16.f32 " \
        "{%0,%1,%2,%3}, {%4,%5,%6,%7}, {%8,%9}, {%0,%1,%2,%3};" \
        : "+f"((d)[0]), "+f"((d)[1]), "+f"((d)[2]), "+f"((d)[3]) \
        : "r"((a)[0]), "r"((a)[1]), "r"((a)[2]), "r"((a)[3]), "r"(b0), "r"(b1))

__device__ __forceinline__ uint16_t bfu(__nv_bfloat16 h) { return __bfloat16_as_ushort(h); }

__device__ __forceinline__ void pack_hl(float a, float b, uint32_t& hi, uint32_t& lo) {
    __nv_bfloat16 ha = __float2bfloat16_rn(a), hb = __float2bfloat16_rn(b);
    __nv_bfloat16 la = __float2bfloat16_rn(a - __bfloat162float(ha));
    __nv_bfloat16 lb = __float2bfloat16_rn(b - __bfloat162float(hb));
    hi = (uint32_t)bfu(ha) | ((uint32_t)bfu(hb) << 16);
    lo = (uint32_t)bfu(la) | ((uint32_t)bfu(lb) << 16);
}

// split float4 into packed hi/lo bf16 (2x uint2)
__device__ __forceinline__ void split_pack(float4 v, uint2& hi, uint2& lo) {
    pack_hl(v.x, v.y, hi.x, lo.x);
    pack_hl(v.z, v.w, hi.y, lo.y);
}

// GEMM smem tile layout
#define T_AHI 0
#define T_ALO 16384
#define T_BHI 32768
#define T_BLO 49152
#define SM_RB 65536
#define SM_GEMM_TOTAL (65536 + 512)

// attention smem layout (bytes); rows padded to 40 bf16 = 80B
#define A_KH 0
#define A_KL 24320
#define A_VH 48640
#define A_VL 72960
#define A_BH 97280                      // 1859 floats
#define A_CJ 104716                     // 304 ints
#define ATTN_SMEM 105936

// ---------------- prep kernels ----------------------------------------------
__global__ __launch_bounds__(256) void split_x_kernel(const float* __restrict__ x)
{
    int i = blockIdx.x * blockDim.x + threadIdx.x;
    if (i < XSZ / 4) {
        float4 v = ((const float4*)x)[i];
        uint2 hi, lo;
        split_pack(v, hi, lo);
        ((uint2*)g_x_hi)[i] = hi;
        ((uint2*)g_x_lo)[i] = lo;
    }
}

__global__ __launch_bounds__(256) void split_w_kernel(const float* __restrict__ wqkv,
                                                      const float* __restrict__ wout)
{
    int i = blockIdx.x * blockDim.x + threadIdx.x;
    const int NQ4 = 768 * 256 / 4;
    const int NO4 = 256 * 256 / 4;
    if (i < NQ4) {
        float4 v = ((const float4*)wqkv)[i];
        uint2 hi, lo;
        split_pack(v, hi, lo);
        ((uint2*)g_wq_hi)[i] = hi;
        ((uint2*)g_wq_lo)[i] = lo;
    } else if (i < NQ4 + NO4) {
        int j = i - NQ4;
        float4 v = ((const float4*)wout)[j];
        uint2 hi, lo;
        split_pack(v, hi, lo);
        ((uint2*)g_wo_hi)[j] = hi;
        ((uint2*)g_wo_lo)[j] = lo;
    }
}

// ---------------------------------------------------------------------------
// Kernel 1: QKV GEMM via mma.sync bf16 3-pass. Epilogue emits bf16 hi/lo.
// grid (6, 3, 256), block 256.
// ---------------------------------------------------------------------------
__global__ __launch_bounds__(256) void qkv_kernel()
{
    extern __shared__ char sm[];
    const uint32_t smb = smem_u32(sm);
    int* rb = (int*)(sm + SM_RB);

    const int bx = blockIdx.x;
    const int by = blockIdx.y;
    const int w  = blockIdx.z;
    const int tid = threadIdx.x;
    const int lane = tid & 31, wid = tid >> 5;
    const int wm = wid & 3, wn = wid >> 2;
    const int hx = w >> 4, wy = w & 15;

    if (tid < 128) {
        int n = by * 128 + tid;
        if (n < NTOK) {
            int l = n / 49; int rem = n - l * 49; int w1 = rem / 7; int w2 = rem - w1 * 7;
            rb[tid] = ((l * 256 + hx * 16 + wy) * 49 + w1 * 7 + w2) * 256;
        } else rb[tid] = -1;
    }
    __syncthreads();

    float acc[2][8][4];
    #pragma unroll
    for (int mt = 0; mt < 2; mt++)
        #pragma unroll
        for (int nt = 0; nt < 8; nt++)
            #pragma unroll
            for (int r = 0; r < 4; r++) acc[mt][nt][r] = 0.f;

    const int l7 = lane & 7;
    const uint32_t arow0 = (uint32_t)(wm * 32 + (lane & 15)) * 128;
    const int cgA = lane >> 4;
    const int g = lane >> 3;
    const uint32_t brow0 = (uint32_t)(wn * 64 + ((g & 2) << 2) + l7) * 128;
    const int cgB = g & 1;

    for (int chunk = 0; chunk < 4; chunk++) {
        #pragma unroll
        for (int i = 0; i < 16; i++) {
            int u = tid + i * 256;
            int tile = u >> 10;
            int uu = u & 1023;
            int row = uu >> 3, kg = uu & 7;
            char* dst = sm + (tile << 14) + row * 128 + ((kg ^ (row & 7)) << 4);
            uint4 val = make_uint4(0u, 0u, 0u, 0u);
            if (tile < 2) {
                int base = rb[row];
                if (base >= 0) {
                    const __nv_bfloat16* src = (tile == 0 ? g_x_hi : g_x_lo)
                                               + base + chunk * 64 + kg * 8;
                    val = *(const uint4*)src;
                }
            } else {
                int nrow = bx * 128 + row;
                const __nv_bfloat16* src = (tile == 2 ? g_wq_hi : g_wq_lo)
                                           + nrow * 256 + chunk * 64 + kg * 8;
                val = *(const uint4*)src;
            }
            *(uint4*)dst = val;
        }
        __syncthreads();

        #pragma unroll
        for (int ks = 0; ks < 4; ks++) {
            uint32_t ah[2][4], al[2][4], bh[4][4], bl[4][4];
            uint32_t aswz = (uint32_t)((ks * 2 + cgA) ^ l7) << 4;
            LDSM4(ah[0], smb + T_AHI + arow0 + aswz);
            LDSM4(ah[1], smb + T_AHI + arow0 + 2048 + aswz);
            LDSM4(al[0], smb + T_ALO + arow0 + aswz);
            LDSM4(al[1], smb + T_ALO + arow0 + 2048 + aswz);
            uint32_t bswz = (uint32_t)((ks * 2 + cgB) ^ l7) << 4;
            #pragma unroll
            for (int p = 0; p < 4; p++) {
                LDSM4(bh[p], smb + T_BHI + brow0 + p * 2048 + bswz);
                LDSM4(bl[p], smb + T_BLO + brow0 + p * 2048 + bswz);
            }
            #pragma unroll
            for (int mt = 0; mt < 2; mt++)
                #pragma unroll
                for (int nt = 0; nt < 8; nt++) {
                    uint32_t h0 = bh[nt >> 1][(nt & 1) * 2], h1 = bh[nt >> 1][(nt & 1) * 2 + 1];
                    uint32_t lo0 = bl[nt >> 1][(nt & 1) * 2], lo1 = bl[nt >> 1][(nt & 1) * 2 + 1];
                    MMA16816(acc[mt][nt], ah[mt], h0, h1);
                    MMA16816(acc[mt][nt], al[mt], h0, h1);
                    MMA16816(acc[mt][nt], ah[mt], lo0, lo1);
                }
        }
        __syncthreads();
    }

    // ---- epilogue: split + scatter to bf16 hi/lo q/k/v ---------------------
    const int part = bx >> 1;
    __nv_bfloat16* dh_ = (part == 0) ? g_qh : (part == 1) ? g_kh : g_vh;
    __nv_bfloat16* dl_ = (part == 0) ? g_ql : (part == 1) ? g_kl : g_vl;
    const float scale = (part == 0) ? QSCALE : 1.f;
    const int trow = lane >> 2;
    const int tcol2 = (lane & 3) * 2;

    #pragma unroll
    for (int mt = 0; mt < 2; mt++) {
        #pragma unroll
        for (int half = 0; half < 2; half++) {
            int r = by * 128 + wm * 32 + mt * 16 + trow + half * 8;
            if (r >= NTOK) continue;
            #pragma unroll
            for (int nt = 0; nt < 8; nt++) {
                int o = bx * 128 + wn * 64 + nt * 8 + tcol2;
                int hh = (o & 255) >> 5, d = o & 31;
                uint32_t hip, lop;
                pack_hl(acc[mt][nt][half * 2] * scale,
                        acc[mt][nt][half * 2 + 1] * scale, hip, lop);
                size_t off = ((size_t)(w * 8 + hh) * NTOK + r) * 32 + d;
                *(uint32_t*)(dh_ + off) = hip;
                *(uint32_t*)(dl_ + off) = lop;
            }
        }
    }
}

// ---------------------------------------------------------------------------
// Kernel 2: tensor-core attention. One CTA per (window, head), 320 threads.
// __launch_bounds__(320, 2): cap regs so 2 CTAs co-reside (occupancy fix).
// V fragments hoisted above exp/pack so LDS latency hides under MUFU work.
// ---------------------------------------------------------------------------
__global__ __launch_bounds__(320, 2) void attn_kernel(const float* __restrict__ bias_table)
{
    extern __shared__ char sm[];
    const uint32_t smb = smem_u32(sm);
    float* bH  = (float*)(sm + A_BH);
    int*   cjs = (int*)(sm + A_CJ);

    const int wh = blockIdx.x;
    const int h  = wh & 7;
    const int w  = wh >> 3;
    const int tid = threadIdx.x;
    const int lane = tid & 31, wm = tid >> 5;
    const int t4 = lane & 3, g = lane >> 2;
    const size_t base = (size_t)wh * NTOK * DH;

    // ---- stage K/V hi/lo into smem (80B row stride, pad rows zeroed) ------
    {
        const __nv_bfloat16* srcs[4] = {g_kh + base, g_kl + base, g_vh + base, g_vl + base};
        const uint32_t dsts[4] = {A_KH, A_KL, A_VH, A_VL};
        for (int idx = tid; idx < 4 * NTOKP * 4; idx += 320) {
            int arr = idx / (NTOKP * 4);
            int rem = idx - arr * (NTOKP * 4);
            int row = rem >> 2, seg = rem & 3;
            uint4 val = make_uint4(0u, 0u, 0u, 0u);
            if (row < NTOK) val = *(const uint4*)(srcs[arr] + row * 32 + seg * 8);
            *(uint4*)(sm + dsts[arr] + row * 80 + seg * 16) = val;
        }
        for (int i = tid; i < NBIAS; i += 320) bH[i] = bias_table[i * HEADS + h];
        for (int i = tid; i < NTOKP; i += 320) {
            if (i < NTOK) {
                int l = i / 49, rem = i - l * 49, w1 = rem / 7, w2 = rem - w1 * 7;
                cjs[i] = l * 169 + w1 * 13 + w2;
            } else cjs[i] = 0;
        }
    }

    // ---- load Q fragments directly from gmem (bf16 hi/lo) -----------------
    const int R = wm * 32;
    uint32_t aQh[2][2][4], aQl[2][2][4];
    #pragma unroll
    for (int mt = 0; mt < 2; mt++) {
        int r0 = R + mt * 16 + g, r1 = r0 + 8;
        #pragma unroll
        for (int kh = 0; kh < 2; kh++) {
            int c0 = kh * 16 + 2 * t4, c1 = c0 + 8;
            aQh[mt][kh][0] = (r0 < NTOK) ? *(const uint32_t*)(g_qh + base + r0 * 32 + c0) : 0u;
            aQh[mt][kh][1] = (r1 < NTOK) ? *(const uint32_t*)(g_qh + base + r1 * 32 + c0) : 0u;
            aQh[mt][kh][2] = (r0 < NTOK) ? *(const uint32_t*)(g_qh + base + r0 * 32 + c1) : 0u;
            aQh[mt][kh][3] = (r1 < NTOK) ? *(const uint32_t*)(g_qh + base + r1 * 32 + c1) : 0u;
            aQl[mt][kh][0] = (r0 < NTOK) ? *(const uint32_t*)(g_ql + base + r0 * 32 + c0) : 0u;
            aQl[mt][kh][1] = (r1 < NTOK) ? *(const uint32_t*)(g_ql + base + r1 * 32 + c0) : 0u;
            aQl[mt][kh][2] = (r0 < NTOK) ? *(const uint32_t*)(g_ql + base + r0 * 32 + c1) : 0u;
            aQl[mt][kh][3] = (r1 < NTOK) ? *(const uint32_t*)(g_ql + base + r1 * 32 + c1) : 0u;
        }
    }
    __syncthreads();

    // row-position codes (+929) for bias; pad rows use row 293's (harmless)
    int ci[2][2];
    #pragma unroll
    for (int mt = 0; mt < 2; mt++) {
        int r0 = R + mt * 16 + g, r1 = r0 + 8;
        ci[mt][0] = cjs[r0 < NTOK ? r0 : NTOK - 1] + 929;
        ci[mt][1] = cjs[r1 < NTOK ? r1 : NTOK - 1] + 929;
    }

    float O[2][4][4];
    #pragma unroll
    for (int mt = 0; mt < 2; mt++)
        #pragma unroll
        for (int dn = 0; dn < 4; dn++)
            #pragma unroll
            for (int e = 0; e < 4; e++) O[mt][dn][e] = 0.f;
    float rs[2][2] = {{0.f, 0.f}, {0.f, 0.f}};

    const int lrow = ((lane & 8) ? 8 : 0) + (lane & 7);
    const int lcol = (lane & 16) ? 8 : 0;

    for (int j0 = 0; j0 < NTOKP; j0 += 16) {
        // ---- K b-fragments ------------------------------------------------
        uint32_t bkh[2][2][2], bkl[2][2][2];    // [jn][kh][b0/b1]
        #pragma unroll
        for (int kh = 0; kh < 2; kh++) {
            uint32_t addr = (uint32_t)((j0 + lrow) * 80 + (kh * 16 + lcol) * 2);
            uint32_t t[4];
            LDSM4(t, smb + A_KH + addr);
            bkh[0][kh][0] = t[0]; bkh[0][kh][1] = t[2];
            bkh[1][kh][0] = t[1]; bkh[1][kh][1] = t[3];
            LDSM4(t, smb + A_KL + addr);
            bkl[0][kh][0] = t[0]; bkl[0][kh][1] = t[2];
            bkl[1][kh][0] = t[1]; bkl[1][kh][1] = t[3];
        }

        // ---- V b-fragments (trans) — hoisted; independent of S ------------
        uint32_t bvh[4][2], bvl[4][2];          // [dn][b0/b1]
        #pragma unroll
        for (int dh2 = 0; dh2 < 2; dh2++) {
            uint32_t addr = (uint32_t)((j0 + lrow) * 80 + (dh2 * 16 + lcol) * 2);
            uint32_t t[4];
            LDSM4T(t, smb + A_VH + addr);
            bvh[dh2 * 2][0] = t[0]; bvh[dh2 * 2][1] = t[1];
            bvh[dh2 * 2 + 1][0] = t[2]; bvh[dh2 * 2 + 1][1] = t[3];
            LDSM4T(t, smb + A_VL + addr);
            bvl[dh2 * 2][0] = t[0]; bvl[dh2 * 2][1] = t[1];
            bvl[dh2 * 2 + 1][0] = t[2]; bvl[dh2 * 2 + 1][1] = t[3];
        }

        // ---- S = Q K^T (3-pass hi/lo) ------------------------------------
        float S[2][2][4];
        #pragma unroll
        for (int mt = 0; mt < 2; mt++)
            #pragma unroll
            for (int jn = 0; jn < 2; jn++) {
                #pragma unroll
                for (int e = 0; e < 4; e++) S[mt][jn][e] = 0.f;
                #pragma unroll
                for (int kh = 0; kh < 2; kh++) {
                    MMA16816(S[mt][jn], aQh[mt][kh], bkh[jn][kh][0], bkh[jn][kh][1]);
                    MMA16816(S[mt][jn], aQl[mt][kh], bkh[jn][kh][0], bkh[jn][kh][1]);
                    MMA16816(S[mt][jn], aQh[mt][kh], bkl[jn][kh][0], bkl[jn][kh][1]);
                }
            }

        // ---- P = exp(S + bias), masked; pack to bf16 hi/lo A-frags -------
        int   jb[2];
        int   cjv[2][2];
        bool  va[2][2];
        #pragma unroll
        for (int jn = 0; jn < 2; jn++) {
            jb[jn] = j0 + 8 * jn + 2 * t4;
            cjv[jn][0] = cjs[jb[jn]];
            cjv[jn][1] = cjs[jb[jn] + 1];
            va[jn][0] = (jb[jn] < NTOK);
            va[jn][1] = (jb[jn] + 1 < NTOK);
        }
        uint32_t aPh[2][4], aPl[2][4];
        #pragma unroll
        for (int mt = 0; mt < 2; mt++) {
            float p[2][4];
            #pragma unroll
            for (int jn = 0; jn < 2; jn++) {
                p[jn][0] = va[jn][0] ? __expf(S[mt][jn][0] + bH[ci[mt][0] - cjv[jn][0]]) : 0.f;
                p[jn][1] = va[jn][1] ? __expf(S[mt][jn][1] + bH[ci[mt][0] - cjv[jn][1]]) : 0.f;
                p[jn][2] = va[jn][0] ? __expf(S[mt][jn][2] + bH[ci[mt][1] - cjv[jn][0]]) : 0.f;
                p[jn][3] = va[jn][1] ? __expf(S[mt][jn][3] + bH[ci[mt][1] - cjv[jn][1]]) : 0.f;
                rs[mt][0] += p[jn][0] + p[jn][1];
                rs[mt][1] += p[jn][2] + p[jn][3];
            }
            pack_hl(p[0][0], p[0][1], aPh[mt][0], aPl[mt][0]);
            pack_hl(p[0][2], p[0][3], aPh[mt][1], aPl[mt][1]);
            pack_hl(p[1][0], p[1][1], aPh[mt][2], aPl[mt][2]);
            pack_hl(p[1][2], p[1][3], aPh[mt][3], aPl[mt][3]);
        }

        // ---- O += P V (3-pass hi/lo) -------------------------------------
        #pragma unroll
        for (int mt = 0; mt < 2; mt++)
            #pragma unroll
            for (int dn = 0; dn < 4; dn++) {
                MMA16816(O[mt][dn], aPh[mt], bvh[dn][0], bvh[dn][1]);
                MMA16816(O[mt][dn], aPl[mt], bvh[dn][0], bvh[dn][1]);
                MMA16816(O[mt][dn], aPh[mt], bvl[dn][0], bvl[dn][1]);
            }
    }

    // ---- normalize + write g_o (fp32) -------------------------------------
    #pragma unroll
    for (int mt = 0; mt < 2; mt++)
        #pragma unroll
        for (int h2 = 0; h2 < 2; h2++) {
            float v = rs[mt][h2];
            v += __shfl_xor_sync(0xFFFFFFFFu, v, 1);
            v += __shfl_xor_sync(0xFFFFFFFFu, v, 2);
            rs[mt][h2] = 1.f / v;
        }
    #pragma unroll
    for (int mt = 0; mt < 2; mt++)
        #pragma unroll
        for (int h2 = 0; h2 < 2; h2++) {
            int row = R + mt * 16 + g + 8 * h2;
            if (row >= NTOK) continue;
            float inv = rs[mt][h2];
            float* dst = g_o + ((size_t)w * NTOK + row) * DIM + h * DH;
            #pragma unroll
            for (int dn = 0; dn < 4; dn++) {
                int col = dn * 8 + 2 * t4;
                *(float2*)(dst + col) = make_float2(O[mt][dn][h2 * 2] * inv,
                                                    O[mt][dn][h2 * 2 + 1] * inv);
            }
        }
}

// ---------------------------------------------------------------------------
// Kernel 3: output GEMM via mma.sync bf16 3-pass, staging splits fp32 g_o.
// grid (2, 3, 256), block 256.
// ---------------------------------------------------------------------------
__global__ __launch_bounds__(256) void out_kernel(float* __restrict__ out)
{
    extern __shared__ char sm[];
    const uint32_t smb = smem_u32(sm);

    const int bx = blockIdx.x;
    const int by = blockIdx.y;
    const int w  = blockIdx.z;
    const int tid = threadIdx.x;
    const int lane = tid & 31, wid = tid >> 5;
    const int wm = wid & 3, wn = wid >> 2;
    const int hx = w >> 4, wy = w & 15;

    float acc[2][8][4];
    #pragma unroll
    for (int mt = 0; mt < 2; mt++)
        #pragma unroll
        for (int nt = 0; nt < 8; nt++)
            #pragma unroll
            for (int r = 0; r < 4; r++) acc[mt][nt][r] = 0.f;

    const int l7 = lane & 7;
    const uint32_t arow0 = (uint32_t)(wm * 32 + (lane & 15)) * 128;
    const int cgA = lane >> 4;
    const int g = lane >> 3;
    const uint32_t brow0 = (uint32_t)(wn * 64 + ((g & 2) << 2) + l7) * 128;
    const int cgB = g & 1;

    for (int chunk = 0; chunk < 4; chunk++) {
        #pragma unroll
        for (int i = 0; i < 4; i++) {
            int u = tid + i * 256;
            int row = u >> 3, kg = u & 7;
            uint32_t off = row * 128 + ((kg ^ (row & 7)) << 4);
            uint4 hi4 = make_uint4(0u, 0u, 0u, 0u);
            uint4 lo4 = make_uint4(0u, 0u, 0u, 0u);
            int tok = by * 128 + row;
            if (tok < NTOK) {
                const float* src = g_o + ((size_t)w * NTOK + tok) * DIM + chunk * 64 + kg * 8;
                float4 v0 = *(const float4*)src;
                float4 v1 = *(const float4*)(src + 4);
                uint2 h0, l0, h1, l1;
                split_pack(v0, h0, l0);
                split_pack(v1, h1, l1);
                hi4 = make_uint4(h0.x, h0.y, h1.x, h1.y);
                lo4 = make_uint4(l0.x, l0.y, l1.x, l1.y);
            }
            *(uint4*)(sm + T_AHI + off) = hi4;
            *(uint4*)(sm + T_ALO + off) = lo4;
        }
        #pragma unroll
        for (int i = 0; i < 8; i++) {
            int u = tid + i * 256;
            int half = u >> 10;
            int uu = u & 1023;
            int row = uu >> 3, kg = uu & 7;
            char* dst = sm + (half ? T_BLO : T_BHI) + row * 128 + ((kg ^ (row & 7)) << 4);
            int nrow = bx * 128 + row;
            const __nv_bfloat16* src = (half ? g_wo_lo : g_wo_hi)
                                       + nrow * 256 + chunk * 64 + kg * 8;
            *(uint4*)dst = *(const uint4*)src;
        }
        __syncthreads();

        #pragma unroll
        for (int ks = 0; ks < 4; ks++) {
            uint32_t ah[2][4], al[2][4], bh[4][4], bl[4][4];
            uint32_t aswz = (uint32_t)((ks * 2 + cgA) ^ l7) << 4;
            LDSM4(ah[0], smb + T_AHI + arow0 + aswz);
            LDSM4(ah[1], smb + T_AHI + arow0 + 2048 + aswz);
            LDSM4(al[0], smb + T_ALO + arow0 + aswz);
            LDSM4(al[1], smb + T_ALO + arow0 + 2048 + aswz);
            uint32_t bswz = (uint32_t)((ks * 2 + cgB) ^ l7) << 4;
            #pragma unroll
            for (int p = 0; p < 4; p++) {
                LDSM4(bh[p], smb + T_BHI + brow0 + p * 2048 + bswz);
                LDSM4(bl[p], smb + T_BLO + brow0 + p * 2048 + bswz);
            }
            #pragma unroll
            for (int mt = 0; mt < 2; mt++)
                #pragma unroll
                for (int nt = 0; nt < 8; nt++) {
                    uint32_t h0 = bh[nt >> 1][(nt & 1) * 2], h1 = bh[nt >> 1][(nt & 1) * 2 + 1];
                    uint32_t lo0 = bl[nt >> 1][(nt & 1) * 2], lo1 = bl[nt >> 1][(nt & 1) * 2 + 1];
                    MMA16816(acc[mt][nt], ah[mt], h0, h1);
                    MMA16816(acc[mt][nt], al[mt], h0, h1);
                    MMA16816(acc[mt][nt], ah[mt], lo0, lo1);
                }
        }
        __syncthreads();
    }

    const int trow = lane >> 2;
    const int tcol2 = (lane & 3) * 2;
    #pragma unroll
    for (int mt = 0; mt < 2; mt++) {
        #pragma unroll
        for (int half = 0; half < 2; half++) {
            int r = by * 128 + wm * 32 + mt * 16 + trow + half * 8;
            if (r >= NTOK) continue;
            int l = r / 49; int rem = r - l * 49; int w1 = rem / 7; int w2 = rem - w1 * 7;
            int ob = ((l * 256 + hx * 16 + wy) * 49 + w1 * 7 + w2) * 256;
            #pragma unroll
            for (int nt = 0; nt < 8; nt++) {
                int o = bx * 128 + wn * 64 + nt * 8 + tcol2;
                *(float2*)(out + ob + o) = make_float2(acc[mt][nt][half * 2],
                                                       acc[mt][nt][half * 2 + 1]);
            }
        }
    }
}

// ---------------------------------------------------------------------------
extern "C" void kernel_launch(void* const* d_in, const int* in_sizes, int n_in,
                              void* d_out, int out_size)
{
    const float* x    = (const float*)d_in[0];
    const float* wqkv = (const float*)d_in[1];
    const float* wout = (const float*)d_in[2];
    const float* bias = (const float*)d_in[3];
    float* out = (float*)d_out;

    cudaFuncSetAttribute(attn_kernel, cudaFuncAttributeMaxDynamicSharedMemorySize, ATTN_SMEM);
    cudaFuncSetAttribute(qkv_kernel, cudaFuncAttributeMaxDynamicSharedMemorySize, SM_GEMM_TOTAL);
    cudaFuncSetAttribute(out_kernel, cudaFuncAttributeMaxDynamicSharedMemorySize, SM_GEMM_TOTAL);

    split_x_kernel<<<(XSZ / 4 + 255) / 256, 256>>>(x);
    split_w_kernel<<<(768 * 256 / 4 + 256 * 256 / 4 + 255) / 256, 256>>>(wqkv, wout);
    qkv_kernel<<<dim3(6, 3, 256), 256, SM_GEMM_TOTAL>>>();
    attn_kernel<<<2048, 320, ATTN_SMEM>>>(bias);
    out_kernel<<<dim3(2, 3, 256), 256, SM_GEMM_TOTAL>>>(out);
}

// round 8
// speedup vs baseline: 2.5329x; 1.3906x over previous
#include <cuda_runtime.h>
#include <cuda_bf16.h>
#include <cstdint>

#define NTOK   294
#define NTOKP  304
#define HEADS  8
#define DH     32
#define DIM    256
#define NWIN   256
#define NBIAS  1859
#define QSCALE 0.17677669529663687f  // 32^-0.5
#define XSZ    (6 * 16 * 16 * 7 * 7 * 256)   // 19267584

// ---------------- scratch (allocation-free: __device__ globals) -------------
__device__ __nv_bfloat16 g_x_hi[XSZ];
__device__ __nv_bfloat16 g_x_lo[XSZ];
__device__ __nv_bfloat16 g_wq_hi[768 * 256];
__device__ __nv_bfloat16 g_wq_lo[768 * 256];
__device__ __nv_bfloat16 g_wo_hi[256 * 256];
__device__ __nv_bfloat16 g_wo_lo[256 * 256];
// q/k/v as bf16 hi/lo, layout [wh][NTOK][32]
__device__ __nv_bfloat16 g_qh[NWIN * HEADS * NTOK * DH];
__device__ __nv_bfloat16 g_ql[NWIN * HEADS * NTOK * DH];
__device__ __nv_bfloat16 g_kh[NWIN * HEADS * NTOK * DH];
__device__ __nv_bfloat16 g_kl[NWIN * HEADS * NTOK * DH];
__device__ __nv_bfloat16 g_vh[NWIN * HEADS * NTOK * DH];
__device__ __nv_bfloat16 g_vl[NWIN * HEADS * NTOK * DH];
// attention output as bf16 hi/lo, layout [w][tok][256]
__device__ __nv_bfloat16 g_oh[NWIN * NTOK * DIM];
__device__ __nv_bfloat16 g_ol[NWIN * NTOK * DIM];

// ---------------- helpers ---------------------------------------------------
__device__ __forceinline__ uint32_t smem_u32(const void* p) {
    uint32_t a;
    asm("{ .reg .u64 t; cvta.to.shared.u64 t, %1; cvt.u32.u64 %0, t; }" : "=r"(a) : "l"(p));
    return a;
}

#define LDSM4(r, a) \
    asm volatile("ldmatrix.sync.aligned.m8n8.x4.shared.b16 {%0,%1,%2,%3}, [%4];" \
        : "=r"((r)[0]), "=r"((r)[1]), "=r"((r)[2]), "=r"((r)[3]) : "r"(a))
#define LDSM4T(r, a) \
    asm volatile("ldmatrix.sync.aligned.m8n8.x4.trans.shared.b16 {%0,%1,%2,%3}, [%4];" \
        : "=r"((r)[0]), "=r"((r)[1]), "=r"((r)[2]), "=r"((r)[3]) : "r"(a))

#define MMA16816(d, a, b0, b1) \
    asm volatile("mma.sync.aligned.m16n8k16.row.col.f32.bf16.bf16.f32 " \
        "{%0,%1,%2,%3}, {%4,%5,%6,%7}, {%8,%9}, {%0,%1,%2,%3};" \
        : "+f"((d)[0]), "+f"((d)[1]), "+f"((d)[2]), "+f"((d)[3]) \
        : "r"((a)[0]), "r"((a)[1]), "r"((a)[2]), "r"((a)[3]), "r"(b0), "r"(b1))

#define CP16(dst, src, sz) \
    asm volatile("cp.async.cg.shared.global [%0], [%1], 16, %2;" \
        :: "r"(dst), "l"(src), "r"(sz))
#define CP_COMMIT() asm volatile("cp.async.commit_group;" ::: "memory")
#define CP_WAIT1()  asm volatile("cp.async.wait_group 1;" ::: "memory")
#define CP_WAIT0()  asm volatile("cp.async.wait_group 0;" ::: "memory")

__device__ __forceinline__ uint16_t bfu(__nv_bfloat16 h) { return __bfloat16_as_ushort(h); }

__device__ __forceinline__ void pack_hl(float a, float b, uint32_t& hi, uint32_t& lo) {
    __nv_bfloat16 ha = __float2bfloat16_rn(a), hb = __float2bfloat16_rn(b);
    __nv_bfloat16 la = __float2bfloat16_rn(a - __bfloat162float(ha));
    __nv_bfloat16 lb = __float2bfloat16_rn(b - __bfloat162float(hb));
    hi = (uint32_t)bfu(ha) | ((uint32_t)bfu(hb) << 16);
    lo = (uint32_t)bfu(la) | ((uint32_t)bfu(lb) << 16);
}

__device__ __forceinline__ void split_pack(float4 v, uint2& hi, uint2& lo) {
    pack_hl(v.x, v.y, hi.x, lo.x);
    pack_hl(v.z, v.w, hi.y, lo.y);
}

// GEMM smem: 2 stages x (AHI|ALO|BHI|BLO) of 16KB each
#define STAGE_BYTES 65536
#define T_AHI 0
#define T_ALO 16384
#define T_BHI 32768
#define T_BLO 49152
#define SM_RB (2 * STAGE_BYTES)
#define SM_GEMM_TOTAL (2 * STAGE_BYTES + 512)

// attention smem layout (bytes); rows padded to 40 bf16 = 80B
#define A_KH 0
#define A_KL 24320
#define A_VH 48640
#define A_VL 72960
#define A_BH 97280                      // 1859 floats
#define A_CJ 104716                     // 304 ints
#define ATTN_SMEM 105936

// ---------------- prep kernels ----------------------------------------------
__global__ __launch_bounds__(256) void split_x_kernel(const float* __restrict__ x)
{
    int i = blockIdx.x * blockDim.x + threadIdx.x;
    if (i < XSZ / 4) {
        float4 v = ((const float4*)x)[i];
        uint2 hi, lo;
        split_pack(v, hi, lo);
        ((uint2*)g_x_hi)[i] = hi;
        ((uint2*)g_x_lo)[i] = lo;
    }
}

__global__ __launch_bounds__(256) void split_w_kernel(const float* __restrict__ wqkv,
                                                      const float* __restrict__ wout)
{
    int i = blockIdx.x * blockDim.x + threadIdx.x;
    const int NQ4 = 768 * 256 / 4;
    const int NO4 = 256 * 256 / 4;
    if (i < NQ4) {
        float4 v = ((const float4*)wqkv)[i];
        uint2 hi, lo;
        split_pack(v, hi, lo);
        ((uint2*)g_wq_hi)[i] = hi;
        ((uint2*)g_wq_lo)[i] = lo;
    } else if (i < NQ4 + NO4) {
        int j = i - NQ4;
        float4 v = ((const float4*)wout)[j];
        uint2 hi, lo;
        split_pack(v, hi, lo);
        ((uint2*)g_wo_hi)[j] = hi;
        ((uint2*)g_wo_lo)[j] = lo;
    }
}

// ---------------- stage loaders (cp.async, 16B granules) --------------------
__device__ __forceinline__ void qkv_stage(uint32_t smb, int stg, int chunk,
                                          const int* rb, int bx, int tid)
{
    #pragma unroll
    for (int i = 0; i < 16; i++) {
        int u = tid + i * 256;
        int tile = u >> 10;
        int uu = u & 1023;
        int row = uu >> 3, kg = uu & 7;
        uint32_t dst = smb + (uint32_t)stg * STAGE_BYTES + (tile << 14)
                       + row * 128 + ((kg ^ (row & 7)) << 4);
        const __nv_bfloat16* src;
        uint32_t sz = 16;
        if (tile < 2) {
            int base = rb[row];
            if (base < 0) { sz = 0; base = 0; }
            src = (tile == 0 ? g_x_hi : g_x_lo) + base + chunk * 64 + kg * 8;
        } else {
            int nrow = bx * 128 + row;
            src = (tile == 2 ? g_wq_hi : g_wq_lo) + nrow * 256 + chunk * 64 + kg * 8;
        }
        CP16(dst, src, sz);
    }
}

__device__ __forceinline__ void out_stage(uint32_t smb, int stg, int chunk,
                                          int bx, int by, int w, int tid)
{
    #pragma unroll
    for (int i = 0; i < 16; i++) {
        int u = tid + i * 256;
        int tile = u >> 10;
        int uu = u & 1023;
        int row = uu >> 3, kg = uu & 7;
        uint32_t dst = smb + (uint32_t)stg * STAGE_BYTES + (tile << 14)
                       + row * 128 + ((kg ^ (row & 7)) << 4);
        const __nv_bfloat16* src;
        uint32_t sz = 16;
        if (tile < 2) {
            int tok = by * 128 + row;
            size_t base = 0;
            if (tok < NTOK) base = ((size_t)w * NTOK + tok) * DIM;
            else sz = 0;
            src = (tile == 0 ? g_oh : g_ol) + base + chunk * 64 + kg * 8;
        } else {
            int nrow = bx * 128 + row;
            src = (tile == 2 ? g_wo_hi : g_wo_lo) + nrow * 256 + chunk * 64 + kg * 8;
        }
        CP16(dst, src, sz);
    }
}

// ---------------------------------------------------------------------------
// Kernel 1: QKV GEMM, cp.async 2-stage pipeline + mma.sync bf16 3-pass.
// grid (6, 3, 256), block 256.
// ---------------------------------------------------------------------------
__global__ __launch_bounds__(256) void qkv_kernel()
{
    extern __shared__ char sm[];
    const uint32_t smb = smem_u32(sm);
    int* rb = (int*)(sm + SM_RB);

    const int bx = blockIdx.x;
    const int by = blockIdx.y;
    const int w  = blockIdx.z;
    const int tid = threadIdx.x;
    const int lane = tid & 31, wid = tid >> 5;
    const int wm = wid & 3, wn = wid >> 2;
    const int hx = w >> 4, wy = w & 15;

    if (tid < 128) {
        int n = by * 128 + tid;
        if (n < NTOK) {
            int l = n / 49; int rem = n - l * 49; int w1 = rem / 7; int w2 = rem - w1 * 7;
            rb[tid] = ((l * 256 + hx * 16 + wy) * 49 + w1 * 7 + w2) * 256;
        } else rb[tid] = -1;
    }
    __syncthreads();

    float acc[2][8][4];
    #pragma unroll
    for (int mt = 0; mt < 2; mt++)
        #pragma unroll
        for (int nt = 0; nt < 8; nt++)
            #pragma unroll
            for (int r = 0; r < 4; r++) acc[mt][nt][r] = 0.f;

    const int l7 = lane & 7;
    const uint32_t arow0 = (uint32_t)(wm * 32 + (lane & 15)) * 128;
    const int cgA = lane >> 4;
    const int g = lane >> 3;
    const uint32_t brow0 = (uint32_t)(wn * 64 + ((g & 2) << 2) + l7) * 128;
    const int cgB = g & 1;

    qkv_stage(smb, 0, 0, rb, bx, tid);
    CP_COMMIT();

    for (int chunk = 0; chunk < 4; chunk++) {
        if (chunk < 3) {
            qkv_stage(smb, (chunk + 1) & 1, chunk + 1, rb, bx, tid);
            CP_COMMIT();
            CP_WAIT1();
        } else {
            CP_WAIT0();
        }
        __syncthreads();

        const uint32_t sb = smb + (uint32_t)(chunk & 1) * STAGE_BYTES;
        #pragma unroll
        for (int ks = 0; ks < 4; ks++) {
            uint32_t ah[2][4], al[2][4], bh[4][4], bl[4][4];
            uint32_t aswz = (uint32_t)((ks * 2 + cgA) ^ l7) << 4;
            LDSM4(ah[0], sb + T_AHI + arow0 + aswz);
            LDSM4(ah[1], sb + T_AHI + arow0 + 2048 + aswz);
            LDSM4(al[0], sb + T_ALO + arow0 + aswz);
            LDSM4(al[1], sb + T_ALO + arow0 + 2048 + aswz);
            uint32_t bswz = (uint32_t)((ks * 2 + cgB) ^ l7) << 4;
            #pragma unroll
            for (int p = 0; p < 4; p++) {
                LDSM4(bh[p], sb + T_BHI + brow0 + p * 2048 + bswz);
                LDSM4(bl[p], sb + T_BLO + brow0 + p * 2048 + bswz);
            }
            #pragma unroll
            for (int mt = 0; mt < 2; mt++)
                #pragma unroll
                for (int nt = 0; nt < 8; nt++) {
                    uint32_t h0 = bh[nt >> 1][(nt & 1) * 2], h1 = bh[nt >> 1][(nt & 1) * 2 + 1];
                    uint32_t lo0 = bl[nt >> 1][(nt & 1) * 2], lo1 = bl[nt >> 1][(nt & 1) * 2 + 1];
                    MMA16816(acc[mt][nt], ah[mt], h0, h1);
                    MMA16816(acc[mt][nt], al[mt], h0, h1);
                    MMA16816(acc[mt][nt], ah[mt], lo0, lo1);
                }
        }
        __syncthreads();
    }

    // ---- epilogue: split + scatter to bf16 hi/lo q/k/v ---------------------
    const int part = bx >> 1;
    __nv_bfloat16* dh_ = (part == 0) ? g_qh : (part == 1) ? g_kh : g_vh;
    __nv_bfloat16* dl_ = (part == 0) ? g_ql : (part == 1) ? g_kl : g_vl;
    const float scale = (part == 0) ? QSCALE : 1.f;
    const int trow = lane >> 2;
    const int tcol2 = (lane & 3) * 2;

    #pragma unroll
    for (int mt = 0; mt < 2; mt++) {
        #pragma unroll
        for (int half = 0; half < 2; half++) {
            int r = by * 128 + wm * 32 + mt * 16 + trow + half * 8;
            if (r >= NTOK) continue;
            #pragma unroll
            for (int nt = 0; nt < 8; nt++) {
                int o = bx * 128 + wn * 64 + nt * 8 + tcol2;
                int hh = (o & 255) >> 5, d = o & 31;
                uint32_t hip, lop;
                pack_hl(acc[mt][nt][half * 2] * scale,
                        acc[mt][nt][half * 2 + 1] * scale, hip, lop);
                size_t off = ((size_t)(w * 8 + hh) * NTOK + r) * 32 + d;
                *(uint32_t*)(dh_ + off) = hip;
                *(uint32_t*)(dl_ + off) = lop;
            }
        }
    }
}

// ---------------------------------------------------------------------------
// Kernel 2: tensor-core attention. One CTA per (window, head), 320 threads.
// Epilogue writes O as bf16 hi/lo (for the pipelined out-GEMM).
// ---------------------------------------------------------------------------
__global__ __launch_bounds__(320, 2) void attn_kernel(const float* __restrict__ bias_table)
{
    extern __shared__ char sm[];
    const uint32_t smb = smem_u32(sm);
    float* bH  = (float*)(sm + A_BH);
    int*   cjs = (int*)(sm + A_CJ);

    const int wh = blockIdx.x;
    const int h  = wh & 7;
    const int w  = wh >> 3;
    const int tid = threadIdx.x;
    const int lane = tid & 31, wm = tid >> 5;
    const int t4 = lane & 3, g = lane >> 2;
    const size_t base = (size_t)wh * NTOK * DH;

    {
        const __nv_bfloat16* srcs[4] = {g_kh + base, g_kl + base, g_vh + base, g_vl + base};
        const uint32_t dsts[4] = {A_KH, A_KL, A_VH, A_VL};
        for (int idx = tid; idx < 4 * NTOKP * 4; idx += 320) {
            int arr = idx / (NTOKP * 4);
            int rem = idx - arr * (NTOKP * 4);
            int row = rem >> 2, seg = rem & 3;
            uint4 val = make_uint4(0u, 0u, 0u, 0u);
            if (row < NTOK) val = *(const uint4*)(srcs[arr] + row * 32 + seg * 8);
            *(uint4*)(sm + dsts[arr] + row * 80 + seg * 16) = val;
        }
        for (int i = tid; i < NBIAS; i += 320) bH[i] = bias_table[i * HEADS + h];
        for (int i = tid; i < NTOKP; i += 320) {
            if (i < NTOK) {
                int l = i / 49, rem = i - l * 49, w1 = rem / 7, w2 = rem - w1 * 7;
                cjs[i] = l * 169 + w1 * 13 + w2;
            } else cjs[i] = 0;
        }
    }

    const int R = wm * 32;
    uint32_t aQh[2][2][4], aQl[2][2][4];
    #pragma unroll
    for (int mt = 0; mt < 2; mt++) {
        int r0 = R + mt * 16 + g, r1 = r0 + 8;
        #pragma unroll
        for (int kh = 0; kh < 2; kh++) {
            int c0 = kh * 16 + 2 * t4, c1 = c0 + 8;
            aQh[mt][kh][0] = (r0 < NTOK) ? *(const uint32_t*)(g_qh + base + r0 * 32 + c0) : 0u;
            aQh[mt][kh][1] = (r1 < NTOK) ? *(const uint32_t*)(g_qh + base + r1 * 32 + c0) : 0u;
            aQh[mt][kh][2] = (r0 < NTOK) ? *(const uint32_t*)(g_qh + base + r0 * 32 + c1) : 0u;
            aQh[mt][kh][3] = (r1 < NTOK) ? *(const uint32_t*)(g_qh + base + r1 * 32 + c1) : 0u;
            aQl[mt][kh][0] = (r0 < NTOK) ? *(const uint32_t*)(g_ql + base + r0 * 32 + c0) : 0u;
            aQl[mt][kh][1] = (r1 < NTOK) ? *(const uint32_t*)(g_ql + base + r1 * 32 + c0) : 0u;
            aQl[mt][kh][2] = (r0 < NTOK) ? *(const uint32_t*)(g_ql + base + r0 * 32 + c1) : 0u;
            aQl[mt][kh][3] = (r1 < NTOK) ? *(const uint32_t*)(g_ql + base + r1 * 32 + c1) : 0u;
        }
    }
    __syncthreads();

    int ci[2][2];
    #pragma unroll
    for (int mt = 0; mt < 2; mt++) {
        int r0 = R + mt * 16 + g, r1 = r0 + 8;
        ci[mt][0] = cjs[r0 < NTOK ? r0 : NTOK - 1] + 929;
        ci[mt][1] = cjs[r1 < NTOK ? r1 : NTOK - 1] + 929;
    }

    float O[2][4][4];
    #pragma unroll
    for (int mt = 0; mt < 2; mt++)
        #pragma unroll
        for (int dn = 0; dn < 4; dn++)
            #pragma unroll
            for (int e = 0; e < 4; e++) O[mt][dn][e] = 0.f;
    float rs[2][2] = {{0.f, 0.f}, {0.f, 0.f}};

    const int lrow = ((lane & 8) ? 8 : 0) + (lane & 7);
    const int lcol = (lane & 16) ? 8 : 0;

    for (int j0 = 0; j0 < NTOKP; j0 += 16) {
        uint32_t bkh[2][2][2], bkl[2][2][2];
        #pragma unroll
        for (int kh = 0; kh < 2; kh++) {
            uint32_t addr = (uint32_t)((j0 + lrow) * 80 + (kh * 16 + lcol) * 2);
            uint32_t t[4];
            LDSM4(t, smb + A_KH + addr);
            bkh[0][kh][0] = t[0]; bkh[0][kh][1] = t[2];
            bkh[1][kh][0] = t[1]; bkh[1][kh][1] = t[3];
            LDSM4(t, smb + A_KL + addr);
            bkl[0][kh][0] = t[0]; bkl[0][kh][1] = t[2];
            bkl[1][kh][0] = t[1]; bkl[1][kh][1] = t[3];
        }

        uint32_t bvh[4][2], bvl[4][2];
        #pragma unroll
        for (int dh2 = 0; dh2 < 2; dh2++) {
            uint32_t addr = (uint32_t)((j0 + lrow) * 80 + (dh2 * 16 + lcol) * 2);
            uint32_t t[4];
            LDSM4T(t, smb + A_VH + addr);
            bvh[dh2 * 2][0] = t[0]; bvh[dh2 * 2][1] = t[1];
            bvh[dh2 * 2 + 1][0] = t[2]; bvh[dh2 * 2 + 1][1] = t[3];
            LDSM4T(t, smb + A_VL + addr);
            bvl[dh2 * 2][0] = t[0]; bvl[dh2 * 2][1] = t[1];
            bvl[dh2 * 2 + 1][0] = t[2]; bvl[dh2 * 2 + 1][1] = t[3];
        }

        float S[2][2][4];
        #pragma unroll
        for (int mt = 0; mt < 2; mt++)
            #pragma unroll
            for (int jn = 0; jn < 2; jn++) {
                #pragma unroll
                for (int e = 0; e < 4; e++) S[mt][jn][e] = 0.f;
                #pragma unroll
                for (int kh = 0; kh < 2; kh++) {
                    MMA16816(S[mt][jn], aQh[mt][kh], bkh[jn][kh][0], bkh[jn][kh][1]);
                    MMA16816(S[mt][jn], aQl[mt][kh], bkh[jn][kh][0], bkh[jn][kh][1]);
                    MMA16816(S[mt][jn], aQh[mt][kh], bkl[jn][kh][0], bkl[jn][kh][1]);
                }
            }

        int   jb[2];
        int   cjv[2][2];
        bool  va[2][2];
        #pragma unroll
        for (int jn = 0; jn < 2; jn++) {
            jb[jn] = j0 + 8 * jn + 2 * t4;
            cjv[jn][0] = cjs[jb[jn]];
            cjv[jn][1] = cjs[jb[jn] + 1];
            va[jn][0] = (jb[jn] < NTOK);
            va[jn][1] = (jb[jn] + 1 < NTOK);
        }
        uint32_t aPh[2][4], aPl[2][4];
        #pragma unroll
        for (int mt = 0; mt < 2; mt++) {
            float p[2][4];
            #pragma unroll
            for (int jn = 0; jn < 2; jn++) {
                p[jn][0] = va[jn][0] ? __expf(S[mt][jn][0] + bH[ci[mt][0] - cjv[jn][0]]) : 0.f;
                p[jn][1] = va[jn][1] ? __expf(S[mt][jn][1] + bH[ci[mt][0] - cjv[jn][1]]) : 0.f;
                p[jn][2] = va[jn][0] ? __expf(S[mt][jn][2] + bH[ci[mt][1] - cjv[jn][0]]) : 0.f;
                p[jn][3] = va[jn][1] ? __expf(S[mt][jn][3] + bH[ci[mt][1] - cjv[jn][1]]) : 0.f;
                rs[mt][0] += p[jn][0] + p[jn][1];
                rs[mt][1] += p[jn][2] + p[jn][3];
            }
            pack_hl(p[0][0], p[0][1], aPh[mt][0], aPl[mt][0]);
            pack_hl(p[0][2], p[0][3], aPh[mt][1], aPl[mt][1]);
            pack_hl(p[1][0], p[1][1], aPh[mt][2], aPl[mt][2]);
            pack_hl(p[1][2], p[1][3], aPh[mt][3], aPl[mt][3]);
        }

        #pragma unroll
        for (int mt = 0; mt < 2; mt++)
            #pragma unroll
            for (int dn = 0; dn < 4; dn++) {
                MMA16816(O[mt][dn], aPh[mt], bvh[dn][0], bvh[dn][1]);
                MMA16816(O[mt][dn], aPl[mt], bvh[dn][0], bvh[dn][1]);
                MMA16816(O[mt][dn], aPh[mt], bvl[dn][0], bvl[dn][1]);
            }
    }

    // ---- normalize + write bf16 hi/lo O -----------------------------------
    #pragma unroll
    for (int mt = 0; mt < 2; mt++)
        #pragma unroll
        for (int h2 = 0; h2 < 2; h2++) {
            float v = rs[mt][h2];
            v += __shfl_xor_sync(0xFFFFFFFFu, v, 1);
            v += __shfl_xor_sync(0xFFFFFFFFu, v, 2);
            rs[mt][h2] = 1.f / v;
        }
    #pragma unroll
    for (int mt = 0; mt < 2; mt++)
        #pragma unroll
        for (int h2 = 0; h2 < 2; h2++) {
            int row = R + mt * 16 + g + 8 * h2;
            if (row >= NTOK) continue;
            float inv = rs[mt][h2];
            size_t ob = ((size_t)w * NTOK + row) * DIM + h * DH;
            #pragma unroll
            for (int dn = 0; dn < 4; dn++) {
                int col = dn * 8 + 2 * t4;
                uint32_t hip, lop;
                pack_hl(O[mt][dn][h2 * 2] * inv, O[mt][dn][h2 * 2 + 1] * inv, hip, lop);
                *(uint32_t*)(g_oh + ob + col) = hip;
                *(uint32_t*)(g_ol + ob + col) = lop;
            }
        }
}

// ---------------------------------------------------------------------------
// Kernel 3: output GEMM, cp.async 2-stage pipeline + mma.sync bf16 3-pass.
// grid (2, 3, 256), block 256.
// ---------------------------------------------------------------------------
__global__ __launch_bounds__(256) void out_kernel(float* __restrict__ out)
{
    extern __shared__ char sm[];
    const uint32_t smb = smem_u32(sm);

    const int bx = blockIdx.x;
    const int by = blockIdx.y;
    const int w  = blockIdx.z;
    const int tid = threadIdx.x;
    const int lane = tid & 31, wid = tid >> 5;
    const int wm = wid & 3, wn = wid >> 2;
    const int hx = w >> 4, wy = w & 15;

    float acc[2][8][4];
    #pragma unroll
    for (int mt = 0; mt < 2; mt++)
        #pragma unroll
        for (int nt = 0; nt < 8; nt++)
            #pragma unroll
            for (int r = 0; r < 4; r++) acc[mt][nt][r] = 0.f;

    const int l7 = lane & 7;
    const uint32_t arow0 = (uint32_t)(wm * 32 + (lane & 15)) * 128;
    const int cgA = lane >> 4;
    const int g = lane >> 3;
    const uint32_t brow0 = (uint32_t)(wn * 64 + ((g & 2) << 2) + l7) * 128;
    const int cgB = g & 1;

    out_stage(smb, 0, 0, bx, by, w, tid);
    CP_COMMIT();

    for (int chunk = 0; chunk < 4; chunk++) {
        if (chunk < 3) {
            out_stage(smb, (chunk + 1) & 1, chunk + 1, bx, by, w, tid);
            CP_COMMIT();
            CP_WAIT1();
        } else {
            CP_WAIT0();
        }
        __syncthreads();

        const uint32_t sb = smb + (uint32_t)(chunk & 1) * STAGE_BYTES;
        #pragma unroll
        for (int ks = 0; ks < 4; ks++) {
            uint32_t ah[2][4], al[2][4], bh[4][4], bl[4][4];
            uint32_t aswz = (uint32_t)((ks * 2 + cgA) ^ l7) << 4;
            LDSM4(ah[0], sb + T_AHI + arow0 + aswz);
            LDSM4(ah[1], sb + T_AHI + arow0 + 2048 + aswz);
            LDSM4(al[0], sb + T_ALO + arow0 + aswz);
            LDSM4(al[1], sb + T_ALO + arow0 + 2048 + aswz);
            uint32_t bswz = (uint32_t)((ks * 2 + cgB) ^ l7) << 4;
            #pragma unroll
            for (int p = 0; p < 4; p++) {
                LDSM4(bh[p], sb + T_BHI + brow0 + p * 2048 + bswz);
                LDSM4(bl[p], sb + T_BLO + brow0 + p * 2048 + bswz);
            }
            #pragma unroll
            for (int mt = 0; mt < 2; mt++)
                #pragma unroll
                for (int nt = 0; nt < 8; nt++) {
                    uint32_t h0 = bh[nt >> 1][(nt & 1) * 2], h1 = bh[nt >> 1][(nt & 1) * 2 + 1];
                    uint32_t lo0 = bl[nt >> 1][(nt & 1) * 2], lo1 = bl[nt >> 1][(nt & 1) * 2 + 1];
                    MMA16816(acc[mt][nt], ah[mt], h0, h1);
                    MMA16816(acc[mt][nt], al[mt], h0, h1);
                    MMA16816(acc[mt][nt], ah[mt], lo0, lo1);
                }
        }
        __syncthreads();
    }

    const int trow = lane >> 2;
    const int tcol2 = (lane & 3) * 2;
    #pragma unroll
    for (int mt = 0; mt < 2; mt++) {
        #pragma unroll
        for (int half = 0; half < 2; half++) {
            int r = by * 128 + wm * 32 + mt * 16 + trow + half * 8;
            if (r >= NTOK) continue;
            int l = r / 49; int rem = r - l * 49; int w1 = rem / 7; int w2 = rem - w1 * 7;
            int ob = ((l * 256 + hx * 16 + wy) * 49 + w1 * 7 + w2) * 256;
            #pragma unroll
            for (int nt = 0; nt < 8; nt++) {
                int o = bx * 128 + wn * 64 + nt * 8 + tcol2;
                *(float2*)(out + ob + o) = make_float2(acc[mt][nt][half * 2],
                                                       acc[mt][nt][half * 2 + 1]);
            }
        }
    }
}

// ---------------------------------------------------------------------------
extern "C" void kernel_launch(void* const* d_in, const int* in_sizes, int n_in,
                              void* d_out, int out_size)
{
    const float* x    = (const float*)d_in[0];
    const float* wqkv = (const float*)d_in[1];
    const float* wout = (const float*)d_in[2];
    const float* bias = (const float*)d_in[3];
    float* out = (float*)d_out;

    cudaFuncSetAttribute(attn_kernel, cudaFuncAttributeMaxDynamicSharedMemorySize, ATTN_SMEM);
    cudaFuncSetAttribute(qkv_kernel, cudaFuncAttributeMaxDynamicSharedMemorySize, SM_GEMM_TOTAL);
    cudaFuncSetAttribute(out_kernel, cudaFuncAttributeMaxDynamicSharedMemorySize, SM_GEMM_TOTAL);

    split_x_kernel<<<(XSZ / 4 + 255) / 256, 256>>>(x);
    split_w_kernel<<<(768 * 256 / 4 + 256 * 256 / 4 + 255) / 256, 256>>>(wqkv, wout);
    qkv_kernel<<<dim3(6, 3, 256), 256, SM_GEMM_TOTAL>>>();
    attn_kernel<<<2048, 320, ATTN_SMEM>>>(bias);
    out_kernel<<<dim3(2, 3, 256), 256, SM_GEMM_TOTAL>>>(out);
}

// round 10
// speedup vs baseline: 3.2795x; 1.2948x over previous
#include <cuda_runtime.h>
#include <cuda_bf16.h>
#include <cstdint>

#define NTOK   294
#define NTOKP  304
#define HEADS  8
#define DH     32
#define DIM    256
#define NWIN   256
#define NBIAS  1859
#define QSCALE 0.17677669529663687f  // 32^-0.5
#define LOG2E  1.4426950408889634f
#define XSZ    (6 * 16 * 16 * 7 * 7 * 256)   // 19267584

// ---------------- scratch (allocation-free: __device__ globals) -------------
__device__ __nv_bfloat16 g_x_hi[XSZ];
__device__ __nv_bfloat16 g_x_lo[XSZ];
__device__ __nv_bfloat16 g_wq_hi[768 * 256];
__device__ __nv_bfloat16 g_wq_lo[768 * 256];
__device__ __nv_bfloat16 g_wo_hi[256 * 256];
__device__ __nv_bfloat16 g_wo_lo[256 * 256];
// q/k/v as bf16 hi/lo, layout [wh][NTOK][32]
__device__ __nv_bfloat16 g_qh[NWIN * HEADS * NTOK * DH];
__device__ __nv_bfloat16 g_ql[NWIN * HEADS * NTOK * DH];
__device__ __nv_bfloat16 g_kh[NWIN * HEADS * NTOK * DH];
__device__ __nv_bfloat16 g_kl[NWIN * HEADS * NTOK * DH];
__device__ __nv_bfloat16 g_vh[NWIN * HEADS * NTOK * DH];
__device__ __nv_bfloat16 g_vl[NWIN * HEADS * NTOK * DH];
// attention output as bf16 hi/lo, layout [w][tok][256]
__device__ __nv_bfloat16 g_oh[NWIN * NTOK * DIM];
__device__ __nv_bfloat16 g_ol[NWIN * NTOK * DIM];

// ---------------- helpers ---------------------------------------------------
__device__ __forceinline__ uint32_t smem_u32(const void* p) {
    uint32_t a;
    asm("{ .reg .u64 t; cvta.to.shared.u64 t, %1; cvt.u32.u64 %0, t; }" : "=r"(a) : "l"(p));
    return a;
}

#define LDSM4(r, a) \
    asm volatile("ldmatrix.sync.aligned.m8n8.x4.shared.b16 {%0,%1,%2,%3}, [%4];" \
        : "=r"((r)[0]), "=r"((r)[1]), "=r"((r)[2]), "=r"((r)[3]) : "r"(a))
#define LDSM4T(r, a) \
    asm volatile("ldmatrix.sync.aligned.m8n8.x4.trans.shared.b16 {%0,%1,%2,%3}, [%4];" \
        : "=r"((r)[0]), "=r"((r)[1]), "=r"((r)[2]), "=r"((r)[3]) : "r"(a))

#define MMA16816(d, a, b0, b1) \
    asm volatile("mma.sync.aligned.m16n8k16.row.col.f32.bf16.bf16.f32 " \
        "{%0,%1,%2,%3}, {%4,%5,%6,%7}, {%8,%9}, {%0,%1,%2,%3};" \
        : "+f"((d)[0]), "+f"((d)[1]), "+f"((d)[2]), "+f"((d)[3]) \
        : "r"((a)[0]), "r"((a)[1]), "r"((a)[2]), "r"((a)[3]), "r"(b0), "r"(b1))

#define CP16(dst, src, sz) \
    asm volatile("cp.async.cg.shared.global [%0], [%1], 16, %2;" \
        :: "r"(dst), "l"(src), "r"(sz))
#define CP_COMMIT() asm volatile("cp.async.commit_group;" ::: "memory")
#define CP_WAIT1()  asm volatile("cp.async.wait_group 1;" ::: "memory")
#define CP_WAIT0()  asm volatile("cp.async.wait_group 0;" ::: "memory")

#define EX2F(d, x) asm("ex2.approx.f32 %0, %1;" : "=f"(d) : "f"(x))

// pack two floats into bf16x2 (one cvt instruction)
__device__ __forceinline__ uint32_t pack2(float lo, float hi) {
    uint32_t r;
    asm("cvt.rn.bf16x2.f32 %0, %1, %2;" : "=r"(r) : "f"(hi), "f"(lo));
    return r;
}
// hi/lo split pair: hi = bf16x2(a,b); lo = bf16x2(a-hi.a, b-hi.b)
__device__ __forceinline__ void pack_hl(float a, float b, uint32_t& hi, uint32_t& lo) {
    hi = pack2(a, b);
    float fa = __uint_as_float(hi << 16);
    float fb = __uint_as_float(hi & 0xffff0000u);
    lo = pack2(a - fa, b - fb);
}
__device__ __forceinline__ void split_pack(float4 v, uint2& hi, uint2& lo) {
    pack_hl(v.x, v.y, hi.x, lo.x);
    pack_hl(v.z, v.w, hi.y, lo.y);
}

// GEMM smem: 2 stages x (AHI|ALO|BHI|BLO) of 16KB each
#define STAGE_BYTES 65536
#define T_AHI 0
#define T_ALO 16384
#define T_BHI 32768
#define T_BLO 49152
#define SM_RB (2 * STAGE_BYTES)
#define SM_GEMM_TOTAL (2 * STAGE_BYTES + 512)

// attention smem layout (bytes); rows padded to 40 bf16 = 80B
#define A_KH 0
#define A_KL 24320
#define A_VH 48640
#define A_VL 72960
#define A_BH 97280                      // 1859 floats (pre-scaled by log2e)
#define A_CJ 104716                     // 304 ints
#define ATTN_SMEM 105936

// ---------------- prep kernels ----------------------------------------------
__global__ __launch_bounds__(256) void split_x_kernel(const float* __restrict__ x)
{
    int i = blockIdx.x * blockDim.x + threadIdx.x;
    if (i < XSZ / 4) {
        float4 v = ((const float4*)x)[i];
        uint2 hi, lo;
        split_pack(v, hi, lo);
        ((uint2*)g_x_hi)[i] = hi;
        ((uint2*)g_x_lo)[i] = lo;
    }
}

__global__ __launch_bounds__(256) void split_w_kernel(const float* __restrict__ wqkv,
                                                      const float* __restrict__ wout)
{
    int i = blockIdx.x * blockDim.x + threadIdx.x;
    const int NQ4 = 768 * 256 / 4;
    const int NO4 = 256 * 256 / 4;
    if (i < NQ4) {
        float4 v = ((const float4*)wqkv)[i];
        uint2 hi, lo;
        split_pack(v, hi, lo);
        ((uint2*)g_wq_hi)[i] = hi;
        ((uint2*)g_wq_lo)[i] = lo;
    } else if (i < NQ4 + NO4) {
        int j = i - NQ4;
        float4 v = ((const float4*)wout)[j];
        uint2 hi, lo;
        split_pack(v, hi, lo);
        ((uint2*)g_wo_hi)[j] = hi;
        ((uint2*)g_wo_lo)[j] = lo;
    }
}

// ---------------- stage loaders (cp.async, 16B granules) --------------------
__device__ __forceinline__ void qkv_stage(uint32_t smb, int stg, int chunk,
                                          const int* rb, int bx, int tid)
{
    #pragma unroll
    for (int i = 0; i < 16; i++) {
        int u = tid + i * 256;
        int tile = u >> 10;
        int uu = u & 1023;
        int row = uu >> 3, kg = uu & 7;
        uint32_t dst = smb + (uint32_t)stg * STAGE_BYTES + (tile << 14)
                       + row * 128 + ((kg ^ (row & 7)) << 4);
        const __nv_bfloat16* src;
        uint32_t sz = 16;
        if (tile < 2) {
            int base = rb[row];
            if (base < 0) { sz = 0; base = 0; }
            src = (tile == 0 ? g_x_hi : g_x_lo) + base + chunk * 64 + kg * 8;
        } else {
            int nrow = bx * 128 + row;
            src = (tile == 2 ? g_wq_hi : g_wq_lo) + nrow * 256 + chunk * 64 + kg * 8;
        }
        CP16(dst, src, sz);
    }
}

__device__ __forceinline__ void out_stage(uint32_t smb, int stg, int chunk,
                                          int bx, int by, int w, int tid)
{
    #pragma unroll
    for (int i = 0; i < 16; i++) {
        int u = tid + i * 256;
        int tile = u >> 10;
        int uu = u & 1023;
        int row = uu >> 3, kg = uu & 7;
        uint32_t dst = smb + (uint32_t)stg * STAGE_BYTES + (tile << 14)
                       + row * 128 + ((kg ^ (row & 7)) << 4);
        const __nv_bfloat16* src;
        uint32_t sz = 16;
        if (tile < 2) {
            int tok = by * 128 + row;
            size_t base = 0;
            if (tok < NTOK) base = ((size_t)w * NTOK + tok) * DIM;
            else sz = 0;
            src = (tile == 0 ? g_oh : g_ol) + base + chunk * 64 + kg * 8;
        } else {
            int nrow = bx * 128 + row;
            src = (tile == 2 ? g_wo_hi : g_wo_lo) + nrow * 256 + chunk * 64 + kg * 8;
        }
        CP16(dst, src, sz);
    }
}

// ---------------------------------------------------------------------------
// Kernel 1: QKV GEMM, cp.async 2-stage pipeline + mma.sync bf16 3-pass.
// grid (6, 3, 256), block 256.
// ---------------------------------------------------------------------------
__global__ __launch_bounds__(256) void qkv_kernel()
{
    extern __shared__ char sm[];
    const uint32_t smb = smem_u32(sm);
    int* rb = (int*)(sm + SM_RB);

    const int bx = blockIdx.x;
    const int by = blockIdx.y;
    const int w  = blockIdx.z;
    const int tid = threadIdx.x;
    const int lane = tid & 31, wid = tid >> 5;
    const int wm = wid & 3, wn = wid >> 2;
    const int hx = w >> 4, wy = w & 15;

    if (tid < 128) {
        int n = by * 128 + tid;
        if (n < NTOK) {
            int l = n / 49; int rem = n - l * 49; int w1 = rem / 7; int w2 = rem - w1 * 7;
            rb[tid] = ((l * 256 + hx * 16 + wy) * 49 + w1 * 7 + w2) * 256;
        } else rb[tid] = -1;
    }
    __syncthreads();

    float acc[2][8][4];
    #pragma unroll
    for (int mt = 0; mt < 2; mt++)
        #pragma unroll
        for (int nt = 0; nt < 8; nt++)
            #pragma unroll
            for (int r = 0; r < 4; r++) acc[mt][nt][r] = 0.f;

    const int l7 = lane & 7;
    const uint32_t arow0 = (uint32_t)(wm * 32 + (lane & 15)) * 128;
    const int cgA = lane >> 4;
    const int g = lane >> 3;
    const uint32_t brow0 = (uint32_t)(wn * 64 + ((g & 2) << 2) + l7) * 128;
    const int cgB = g & 1;

    qkv_stage(smb, 0, 0, rb, bx, tid);
    CP_COMMIT();

    for (int chunk = 0; chunk < 4; chunk++) {
        if (chunk < 3) {
            qkv_stage(smb, (chunk + 1) & 1, chunk + 1, rb, bx, tid);
            CP_COMMIT();
            CP_WAIT1();
        } else {
            CP_WAIT0();
        }
        __syncthreads();

        const uint32_t sb = smb + (uint32_t)(chunk & 1) * STAGE_BYTES;
        #pragma unroll
        for (int ks = 0; ks < 4; ks++) {
            uint32_t ah[2][4], al[2][4], bh[4][4], bl[4][4];
            uint32_t aswz = (uint32_t)((ks * 2 + cgA) ^ l7) << 4;
            LDSM4(ah[0], sb + T_AHI + arow0 + aswz);
            LDSM4(ah[1], sb + T_AHI + arow0 + 2048 + aswz);
            LDSM4(al[0], sb + T_ALO + arow0 + aswz);
            LDSM4(al[1], sb + T_ALO + arow0 + 2048 + aswz);
            uint32_t bswz = (uint32_t)((ks * 2 + cgB) ^ l7) << 4;
            #pragma unroll
            for (int p = 0; p < 4; p++) {
                LDSM4(bh[p], sb + T_BHI + brow0 + p * 2048 + bswz);
                LDSM4(bl[p], sb + T_BLO + brow0 + p * 2048 + bswz);
            }
            #pragma unroll
            for (int mt = 0; mt < 2; mt++)
                #pragma unroll
                for (int nt = 0; nt < 8; nt++) {
                    uint32_t h0 = bh[nt >> 1][(nt & 1) * 2], h1 = bh[nt >> 1][(nt & 1) * 2 + 1];
                    uint32_t lo0 = bl[nt >> 1][(nt & 1) * 2], lo1 = bl[nt >> 1][(nt & 1) * 2 + 1];
                    MMA16816(acc[mt][nt], ah[mt], h0, h1);
                    MMA16816(acc[mt][nt], al[mt], h0, h1);
                    MMA16816(acc[mt][nt], ah[mt], lo0, lo1);
                }
        }
        __syncthreads();
    }

    // ---- epilogue: split + scatter to bf16 hi/lo q/k/v ---------------------
    const int part = bx >> 1;
    __nv_bfloat16* dh_ = (part == 0) ? g_qh : (part == 1) ? g_kh : g_vh;
    __nv_bfloat16* dl_ = (part == 0) ? g_ql : (part == 1) ? g_kl : g_vl;
    const float scale = (part == 0) ? QSCALE : 1.f;
    const int trow = lane >> 2;
    const int tcol2 = (lane & 3) * 2;

    #pragma unroll
    for (int mt = 0; mt < 2; mt++) {
        #pragma unroll
        for (int half = 0; half < 2; half++) {
            int r = by * 128 + wm * 32 + mt * 16 + trow + half * 8;
            if (r >= NTOK) continue;
            #pragma unroll
            for (int nt = 0; nt < 8; nt++) {
                int o = bx * 128 + wn * 64 + nt * 8 + tcol2;
                int hh = (o & 255) >> 5, d = o & 31;
                uint32_t hip, lop;
                pack_hl(acc[mt][nt][half * 2] * scale,
                        acc[mt][nt][half * 2 + 1] * scale, hip, lop);
                size_t off = ((size_t)(w * 8 + hh) * NTOK + r) * 32 + d;
                *(uint32_t*)(dh_ + off) = hip;
                *(uint32_t*)(dl_ + off) = lop;
            }
        }
    }
}

// ---------------------------------------------------------------------------
// Kernel 2: tensor-core attention. One CTA per (window, head), 320 threads.
// Bias prefetched before S; exp via ex2(fma(S, log2e, b*log2e)); cp.async stage.
// ---------------------------------------------------------------------------
__global__ __launch_bounds__(320, 2) void attn_kernel(const float* __restrict__ bias_table)
{
    extern __shared__ char sm[];
    const uint32_t smb = smem_u32(sm);
    float* bH  = (float*)(sm + A_BH);
    int*   cjs = (int*)(sm + A_CJ);

    const int wh = blockIdx.x;
    const int h  = wh & 7;
    const int w  = wh >> 3;
    const int tid = threadIdx.x;
    const int lane = tid & 31, wm = tid >> 5;
    const int t4 = lane & 3, g = lane >> 2;
    const size_t base = (size_t)wh * NTOK * DH;

    // ---- stage K/V via cp.async (overlaps bias/cj/Q loads) ----------------
    {
        const __nv_bfloat16* srcs[4] = {g_kh + base, g_kl + base, g_vh + base, g_vl + base};
        const uint32_t dsts[4] = {A_KH, A_KL, A_VH, A_VL};
        for (int idx = tid; idx < 4 * NTOKP * 4; idx += 320) {
            int arr = idx / (NTOKP * 4);
            int rem = idx - arr * (NTOKP * 4);
            int row = rem >> 2, seg = rem & 3;
            uint32_t sz = (row < NTOK) ? 16u : 0u;
            int srow = (row < NTOK) ? row : 0;
            CP16(smb + dsts[arr] + row * 80 + seg * 16, srcs[arr] + srow * 32 + seg * 8, sz);
        }
        CP_COMMIT();
        for (int i = tid; i < NBIAS; i += 320) bH[i] = bias_table[i * HEADS + h] * LOG2E;
        for (int i = tid; i < NTOKP; i += 320) {
            if (i < NTOK) {
                int l = i / 49, rem = i - l * 49, w1 = rem / 7, w2 = rem - w1 * 7;
                cjs[i] = l * 169 + w1 * 13 + w2;
            } else cjs[i] = 0;
        }
    }

    // ---- load Q fragments directly from gmem (bf16 hi/lo) -----------------
    const int R = wm * 32;
    uint32_t aQh[2][2][4], aQl[2][2][4];
    #pragma unroll
    for (int mt = 0; mt < 2; mt++) {
        int r0 = R + mt * 16 + g, r1 = r0 + 8;
        #pragma unroll
        for (int kh = 0; kh < 2; kh++) {
            int c0 = kh * 16 + 2 * t4, c1 = c0 + 8;
            aQh[mt][kh][0] = (r0 < NTOK) ? *(const uint32_t*)(g_qh + base + r0 * 32 + c0) : 0u;
            aQh[mt][kh][1] = (r1 < NTOK) ? *(const uint32_t*)(g_qh + base + r1 * 32 + c0) : 0u;
            aQh[mt][kh][2] = (r0 < NTOK) ? *(const uint32_t*)(g_qh + base + r0 * 32 + c1) : 0u;
            aQh[mt][kh][3] = (r1 < NTOK) ? *(const uint32_t*)(g_qh + base + r1 * 32 + c1) : 0u;
            aQl[mt][kh][0] = (r0 < NTOK) ? *(const uint32_t*)(g_ql + base + r0 * 32 + c0) : 0u;
            aQl[mt][kh][1] = (r1 < NTOK) ? *(const uint32_t*)(g_ql + base + r1 * 32 + c0) : 0u;
            aQl[mt][kh][2] = (r0 < NTOK) ? *(const uint32_t*)(g_ql + base + r0 * 32 + c1) : 0u;
            aQl[mt][kh][3] = (r1 < NTOK) ? *(const uint32_t*)(g_ql + base + r1 * 32 + c1) : 0u;
        }
    }
    CP_WAIT0();
    __syncthreads();

    int ci[2][2];
    #pragma unroll
    for (int mt = 0; mt < 2; mt++) {
        int r0 = R + mt * 16 + g, r1 = r0 + 8;
        ci[mt][0] = cjs[r0 < NTOK ? r0 : NTOK - 1] + 929;
        ci[mt][1] = cjs[r1 < NTOK ? r1 : NTOK - 1] + 929;
    }

    float O[2][4][4];
    #pragma unroll
    for (int mt = 0; mt < 2; mt++)
        #pragma unroll
        for (int dn = 0; dn < 4; dn++)
            #pragma unroll
            for (int e = 0; e < 4; e++) O[mt][dn][e] = 0.f;
    float rs[2][2] = {{0.f, 0.f}, {0.f, 0.f}};

    const int lrow = ((lane & 8) ? 8 : 0) + (lane & 7);
    const int lcol = (lane & 16) ? 8 : 0;

    for (int j0 = 0; j0 < NTOKP; j0 += 16) {
        // ---- bias/mask prefetch (independent of S) ------------------------
        int   cjv[2][2];
        bool  va[2][2];
        #pragma unroll
        for (int jn = 0; jn < 2; jn++) {
            int jb = j0 + 8 * jn + 2 * t4;
            cjv[jn][0] = cjs[jb];
            cjv[jn][1] = cjs[jb + 1];
            va[jn][0] = (jb < NTOK);
            va[jn][1] = (jb + 1 < NTOK);
        }
        float bb[2][2][4];
        #pragma unroll
        for (int mt = 0; mt < 2; mt++)
            #pragma unroll
            for (int jn = 0; jn < 2; jn++) {
                bb[mt][jn][0] = bH[ci[mt][0] - cjv[jn][0]];
                bb[mt][jn][1] = bH[ci[mt][0] - cjv[jn][1]];
                bb[mt][jn][2] = bH[ci[mt][1] - cjv[jn][0]];
                bb[mt][jn][3] = bH[ci[mt][1] - cjv[jn][1]];
            }

        // ---- K + V fragments ---------------------------------------------
        uint32_t bkh[2][2][2], bkl[2][2][2];
        #pragma unroll
        for (int kh = 0; kh < 2; kh++) {
            uint32_t addr = (uint32_t)((j0 + lrow) * 80 + (kh * 16 + lcol) * 2);
            uint32_t t[4];
            LDSM4(t, smb + A_KH + addr);
            bkh[0][kh][0] = t[0]; bkh[0][kh][1] = t[2];
            bkh[1][kh][0] = t[1]; bkh[1][kh][1] = t[3];
            LDSM4(t, smb + A_KL + addr);
            bkl[0][kh][0] = t[0]; bkl[0][kh][1] = t[2];
            bkl[1][kh][0] = t[1]; bkl[1][kh][1] = t[3];
        }
        uint32_t bvh[4][2], bvl[4][2];
        #pragma unroll
        for (int dh2 = 0; dh2 < 2; dh2++) {
            uint32_t addr = (uint32_t)((j0 + lrow) * 80 + (dh2 * 16 + lcol) * 2);
            uint32_t t[4];
            LDSM4T(t, smb + A_VH + addr);
            bvh[dh2 * 2][0] = t[0]; bvh[dh2 * 2][1] = t[1];
            bvh[dh2 * 2 + 1][0] = t[2]; bvh[dh2 * 2 + 1][1] = t[3];
            LDSM4T(t, smb + A_VL + addr);
            bvl[dh2 * 2][0] = t[0]; bvl[dh2 * 2][1] = t[1];
            bvl[dh2 * 2 + 1][0] = t[2]; bvl[dh2 * 2 + 1][1] = t[3];
        }

        // ---- S = Q K^T (3-pass hi/lo) ------------------------------------
        float S[2][2][4];
        #pragma unroll
        for (int mt = 0; mt < 2; mt++)
            #pragma unroll
            for (int jn = 0; jn < 2; jn++) {
                #pragma unroll
                for (int e = 0; e < 4; e++) S[mt][jn][e] = 0.f;
                #pragma unroll
                for (int kh = 0; kh < 2; kh++) {
                    MMA16816(S[mt][jn], aQh[mt][kh], bkh[jn][kh][0], bkh[jn][kh][1]);
                    MMA16816(S[mt][jn], aQl[mt][kh], bkh[jn][kh][0], bkh[jn][kh][1]);
                    MMA16816(S[mt][jn], aQh[mt][kh], bkl[jn][kh][0], bkl[jn][kh][1]);
                }
            }

        // ---- p = 2^(S*log2e + b*log2e), masked; pack bf16 hi/lo ----------
        uint32_t aPh[2][4], aPl[2][4];
        #pragma unroll
        for (int mt = 0; mt < 2; mt++) {
            float p[2][4];
            #pragma unroll
            for (int jn = 0; jn < 2; jn++) {
                #pragma unroll
                for (int e = 0; e < 4; e++) {
                    float arg = fmaf(S[mt][jn][e], LOG2E, bb[mt][jn][e]);
                    float ex; EX2F(ex, arg);
                    p[jn][e] = va[jn][e & 1] ? ex : 0.f;
                }
                rs[mt][0] += p[jn][0] + p[jn][1];
                rs[mt][1] += p[jn][2] + p[jn][3];
            }
            pack_hl(p[0][0], p[0][1], aPh[mt][0], aPl[mt][0]);
            pack_hl(p[0][2], p[0][3], aPh[mt][1], aPl[mt][1]);
            pack_hl(p[1][0], p[1][1], aPh[mt][2], aPl[mt][2]);
            pack_hl(p[1][2], p[1][3], aPh[mt][3], aPl[mt][3]);
        }

        // ---- O += P V (3-pass hi/lo) -------------------------------------
        #pragma unroll
        for (int mt = 0; mt < 2; mt++)
            #pragma unroll
            for (int dn = 0; dn < 4; dn++) {
                MMA16816(O[mt][dn], aPh[mt], bvh[dn][0], bvh[dn][1]);
                MMA16816(O[mt][dn], aPl[mt], bvh[dn][0], bvh[dn][1]);
                MMA16816(O[mt][dn], aPh[mt], bvl[dn][0], bvl[dn][1]);
            }
    }

    // ---- normalize + write bf16 hi/lo O -----------------------------------
    #pragma unroll
    for (int mt = 0; mt < 2; mt++)
        #pragma unroll
        for (int h2 = 0; h2 < 2; h2++) {
            float v = rs[mt][h2];
            v += __shfl_xor_sync(0xFFFFFFFFu, v, 1);
            v += __shfl_xor_sync(0xFFFFFFFFu, v, 2);
            rs[mt][h2] = 1.f / v;
        }
    #pragma unroll
    for (int mt = 0; mt < 2; mt++)
        #pragma unroll
        for (int h2 = 0; h2 < 2; h2++) {
            int row = R + mt * 16 + g + 8 * h2;
            if (row >= NTOK) continue;
            float inv = rs[mt][h2];
            size_t ob = ((size_t)w * NTOK + row) * DIM + h * DH;
            #pragma unroll
            for (int dn = 0; dn < 4; dn++) {
                int col = dn * 8 + 2 * t4;
                uint32_t hip, lop;
                pack_hl(O[mt][dn][h2 * 2] * inv, O[mt][dn][h2 * 2 + 1] * inv, hip, lop);
                *(uint32_t*)(g_oh + ob + col) = hip;
                *(uint32_t*)(g_ol + ob + col) = lop;
            }
        }
}

// ---------------------------------------------------------------------------
// Kernel 3: output GEMM, cp.async 2-stage pipeline + mma.sync bf16 3-pass.
// grid (2, 3, 256), block 256.
// ---------------------------------------------------------------------------
__global__ __launch_bounds__(256) void out_kernel(float* __restrict__ out)
{
    extern __shared__ char sm[];
    const uint32_t smb = smem_u32(sm);

    const int bx = blockIdx.x;
    const int by = blockIdx.y;
    const int w  = blockIdx.z;
    const int tid = threadIdx.x;
    const int lane = tid & 31, wid = tid >> 5;
    const int wm = wid & 3, wn = wid >> 2;
    const int hx = w >> 4, wy = w & 15;

    float acc[2][8][4];
    #pragma unroll
    for (int mt = 0; mt < 2; mt++)
        #pragma unroll
        for (int nt = 0; nt < 8; nt++)
            #pragma unroll
            for (int r = 0; r < 4; r++) acc[mt][nt][r] = 0.f;

    const int l7 = lane & 7;
    const uint32_t arow0 = (uint32_t)(wm * 32 + (lane & 15)) * 128;
    const int cgA = lane >> 4;
    const int g = lane >> 3;
    const uint32_t brow0 = (uint32_t)(wn * 64 + ((g & 2) << 2) + l7) * 128;
    const int cgB = g & 1;

    out_stage(smb, 0, 0, bx, by, w, tid);
    CP_COMMIT();

    for (int chunk = 0; chunk < 4; chunk++) {
        if (chunk < 3) {
            out_stage(smb, (chunk + 1) & 1, chunk + 1, bx, by, w, tid);
            CP_COMMIT();
            CP_WAIT1();
        } else {
            CP_WAIT0();
        }
        __syncthreads();

        const uint32_t sb = smb + (uint32_t)(chunk & 1) * STAGE_BYTES;
        #pragma unroll
        for (int ks = 0; ks < 4; ks++) {
            uint32_t ah[2][4], al[2][4], bh[4][4], bl[4][4];
            uint32_t aswz = (uint32_t)((ks * 2 + cgA) ^ l7) << 4;
            LDSM4(ah[0], sb + T_AHI + arow0 + aswz);
            LDSM4(ah[1], sb + T_AHI + arow0 + 2048 + aswz);
            LDSM4(al[0], sb + T_ALO + arow0 + aswz);
            LDSM4(al[1], sb + T_ALO + arow0 + 2048 + aswz);
            uint32_t bswz = (uint32_t)((ks * 2 + cgB) ^ l7) << 4;
            #pragma unroll
            for (int p = 0; p < 4; p++) {
                LDSM4(bh[p], sb + T_BHI + brow0 + p * 2048 + bswz);
                LDSM4(bl[p], sb + T_BLO + brow0 + p * 2048 + bswz);
            }
            #pragma unroll
            for (int mt = 0; mt < 2; mt++)
                #pragma unroll
                for (int nt = 0; nt < 8; nt++) {
                    uint32_t h0 = bh[nt >> 1][(nt & 1) * 2], h1 = bh[nt >> 1][(nt & 1) * 2 + 1];
                    uint32_t lo0 = bl[nt >> 1][(nt & 1) * 2], lo1 = bl[nt >> 1][(nt & 1) * 2 + 1];
                    MMA16816(acc[mt][nt], ah[mt], h0, h1);
                    MMA16816(acc[mt][nt], al[mt], h0, h1);
                    MMA16816(acc[mt][nt], ah[mt], lo0, lo1);
                }
        }
        __syncthreads();
    }

    const int trow = lane >> 2;
    const int tcol2 = (lane & 3) * 2;
    #pragma unroll
    for (int mt = 0; mt < 2; mt++) {
        #pragma unroll
        for (int half = 0; half < 2; half++) {
            int r = by * 128 + wm * 32 + mt * 16 + trow + half * 8;
            if (r >= NTOK) continue;
            int l = r / 49; int rem = r - l * 49; int w1 = rem / 7; int w2 = rem - w1 * 7;
            int ob = ((l * 256 + hx * 16 + wy) * 49 + w1 * 7 + w2) * 256;
            #pragma unroll
            for (int nt = 0; nt < 8; nt++) {
                int o = bx * 128 + wn * 64 + nt * 8 + tcol2;
                *(float2*)(out + ob + o) = make_float2(acc[mt][nt][half * 2],
                                                       acc[mt][nt][half * 2 + 1]);
            }
        }
    }
}

// ---------------------------------------------------------------------------
extern "C" void kernel_launch(void* const* d_in, const int* in_sizes, int n_in,
                              void* d_out, int out_size)
{
    const float* x    = (const float*)d_in[0];
    const float* wqkv = (const float*)d_in[1];
    const float* wout = (const float*)d_in[2];
    const float* bias = (const float*)d_in[3];
    float* out = (float*)d_out;

    cudaFuncSetAttribute(attn_kernel, cudaFuncAttributeMaxDynamicSharedMemorySize, ATTN_SMEM);
    cudaFuncSetAttribute(qkv_kernel, cudaFuncAttributeMaxDynamicSharedMemorySize, SM_GEMM_TOTAL);
    cudaFuncSetAttribute(out_kernel, cudaFuncAttributeMaxDynamicSharedMemorySize, SM_GEMM_TOTAL);

    split_x_kernel<<<(XSZ / 4 + 255) / 256, 256>>>(x);
    split_w_kernel<<<(768 * 256 / 4 + 256 * 256 / 4 + 255) / 256, 256>>>(wqkv, wout);
    qkv_kernel<<<dim3(6, 3, 256), 256, SM_GEMM_TOTAL>>>();
    attn_kernel<<<2048, 320, ATTN_SMEM>>>(bias);
    out_kernel<<<dim3(2, 3, 256), 256, SM_GEMM_TOTAL>>>(out);
}

// round 14
// speedup vs baseline: 3.3550x; 1.0230x over previous
#include <cuda_runtime.h>
#include <cuda_bf16.h>
#include <cstdint>

#define NTOK   294
#define NTOKP  304
#define HEADS  8
#define DH     32
#define DIM    256
#define NWIN   256
#define NBIAS  1859
#define QSCALE 0.17677669529663687f  // 32^-0.5
#define LOG2E  1.4426950408889634f
#define XSZ    (6 * 16 * 16 * 7 * 7 * 256)   // 19267584

// ---------------- scratch (allocation-free: __device__ globals) -------------
__device__ __nv_bfloat16 g_x_hi[XSZ];
__device__ __nv_bfloat16 g_x_lo[XSZ];
__device__ __nv_bfloat16 g_wq_hi[768 * 256];
__device__ __nv_bfloat16 g_wq_lo[768 * 256];
__device__ __nv_bfloat16 g_wo_hi[256 * 256];
__device__ __nv_bfloat16 g_wo_lo[256 * 256];
// q/k/v as bf16 hi/lo, layout [wh][NTOK][32]
__device__ __nv_bfloat16 g_qh[NWIN * HEADS * NTOK * DH];
__device__ __nv_bfloat16 g_ql[NWIN * HEADS * NTOK * DH];
__device__ __nv_bfloat16 g_kh[NWIN * HEADS * NTOK * DH];
__device__ __nv_bfloat16 g_kl[NWIN * HEADS * NTOK * DH];
__device__ __nv_bfloat16 g_vh[NWIN * HEADS * NTOK * DH];
__device__ __nv_bfloat16 g_vl[NWIN * HEADS * NTOK * DH];
// attention output as bf16 hi/lo, layout [w][tok][256]
__device__ __nv_bfloat16 g_oh[NWIN * NTOK * DIM];
__device__ __nv_bfloat16 g_ol[NWIN * NTOK * DIM];

// ---------------- helpers ---------------------------------------------------
__device__ __forceinline__ uint32_t smem_u32(const void* p) {
    uint32_t a;
    asm("{ .reg .u64 t; cvta.to.shared.u64 t, %1; cvt.u32.u64 %0, t; }" : "=r"(a) : "l"(p));
    return a;
}

#define LDSM4(r, a) \
    asm volatile("ldmatrix.sync.aligned.m8n8.x4.shared.b16 {%0,%1,%2,%3}, [%4];" \
        : "=r"((r)[0]), "=r"((r)[1]), "=r"((r)[2]), "=r"((r)[3]) : "r"(a))
#define LDSM4T(r, a) \
    asm volatile("ldmatrix.sync.aligned.m8n8.x4.trans.shared.b16 {%0,%1,%2,%3}, [%4];" \
        : "=r"((r)[0]), "=r"((r)[1]), "=r"((r)[2]), "=r"((r)[3]) : "r"(a))

#define MMA16816(d, a, b0, b1) \
    asm volatile("mma.sync.aligned.m16n8k16.row.col.f32.bf16.bf16.f32 " \
        "{%0,%1,%2,%3}, {%4,%5,%6,%7}, {%8,%9}, {%0,%1,%2,%3};" \
        : "+f"((d)[0]), "+f"((d)[1]), "+f"((d)[2]), "+f"((d)[3]) \
        : "r"((a)[0]), "r"((a)[1]), "r"((a)[2]), "r"((a)[3]), "r"(b0), "r"(b1))

#define CP16(dst, src, sz) \
    asm volatile("cp.async.cg.shared.global [%0], [%1], 16, %2;" \
        :: "r"(dst), "l"(src), "r"(sz))
#define CP_COMMIT() asm volatile("cp.async.commit_group;" ::: "memory")
#define CP_WAIT1()  asm volatile("cp.async.wait_group 1;" ::: "memory")
#define CP_WAIT0()  asm volatile("cp.async.wait_group 0;" ::: "memory")

#define EX2F(d, x) asm("ex2.approx.f32 %0, %1;" : "=f"(d) : "f"(x))

// pack two floats into bf16x2 (one cvt instruction)
__device__ __forceinline__ uint32_t pack2(float lo, float hi) {
    uint32_t r;
    asm("cvt.rn.bf16x2.f32 %0, %1, %2;" : "=r"(r) : "f"(hi), "f"(lo));
    return r;
}
// hi/lo split pair
__device__ __forceinline__ void pack_hl(float a, float b, uint32_t& hi, uint32_t& lo) {
    hi = pack2(a, b);
    float fa = __uint_as_float(hi << 16);
    float fb = __uint_as_float(hi & 0xffff0000u);
    lo = pack2(a - fa, b - fb);
}
__device__ __forceinline__ void split_pack(float4 v, uint2& hi, uint2& lo) {
    pack_hl(v.x, v.y, hi.x, lo.x);
    pack_hl(v.z, v.w, hi.y, lo.y);
}

// GEMM smem: 2 stages x (AHI|ALO|BHI|BLO); tile = 128 rows x 32 cols bf16,
// 80B padded row stride (64B data + 16B pad) -> conflict-free, no swizzle.
#define TILE_BYTES 10240                 // 128 * 80
#define STAGE_BYTES 40960                // 4 tiles
#define T_AHI 0
#define T_ALO 10240
#define T_BHI 20480
#define T_BLO 30720
#define SM_RB (2 * STAGE_BYTES)          // 81920
#define SM_GEMM_TOTAL (2 * STAGE_BYTES + 512)

// attention smem layout (bytes); rows padded to 40 bf16 = 80B
#define A_KH 0
#define A_KL 24320
#define A_VH 48640
#define A_VL 72960
#define A_BH 97280                      // 1859 floats (pre-scaled by log2e)
#define A_CJ 104716                     // 304 ints
#define ATTN_SMEM 105936

// ---------------- prep kernels ----------------------------------------------
__global__ __launch_bounds__(256) void split_x_kernel(const float* __restrict__ x)
{
    int i = blockIdx.x * blockDim.x + threadIdx.x;
    if (i < XSZ / 4) {
        float4 v = ((const float4*)x)[i];
        uint2 hi, lo;
        split_pack(v, hi, lo);
        ((uint2*)g_x_hi)[i] = hi;
        ((uint2*)g_x_lo)[i] = lo;
    }
}

__global__ __launch_bounds__(256) void split_w_kernel(const float* __restrict__ wqkv,
                                                      const float* __restrict__ wout)
{
    int i = blockIdx.x * blockDim.x + threadIdx.x;
    const int NQ4 = 768 * 256 / 4;
    const int NO4 = 256 * 256 / 4;
    if (i < NQ4) {
        float4 v = ((const float4*)wqkv)[i];
        uint2 hi, lo;
        split_pack(v, hi, lo);
        ((uint2*)g_wq_hi)[i] = hi;
        ((uint2*)g_wq_lo)[i] = lo;
    } else if (i < NQ4 + NO4) {
        int j = i - NQ4;
        float4 v = ((const float4*)wout)[j];
        uint2 hi, lo;
        split_pack(v, hi, lo);
        ((uint2*)g_wo_hi)[j] = hi;
        ((uint2*)g_wo_lo)[j] = lo;
    }
}

// ---------------- stage loaders (cp.async, 16B granules, 32-col chunks) -----
__device__ __forceinline__ void qkv_stage(uint32_t smb, int stg, int chunk,
                                          const int* rb, int bx, int tid)
{
    #pragma unroll
    for (int i = 0; i < 8; i++) {
        int u = tid + i * 256;               // 0..2047
        int tile = u >> 9;                   // 0..3
        int uu = u & 511;
        int row = uu >> 2, kc = uu & 3;      // row 0..127, 16B granule 0..3
        uint32_t dst = smb + (uint32_t)stg * STAGE_BYTES + tile * TILE_BYTES
                       + row * 80 + kc * 16;
        const __nv_bfloat16* src;
        uint32_t sz = 16;
        if (tile < 2) {
            int base = rb[row];
            if (base < 0) { sz = 0; base = 0; }
            src = (tile == 0 ? g_x_hi : g_x_lo) + base + chunk * 32 + kc * 8;
        } else {
            int nrow = bx * 128 + row;
            src = (tile == 2 ? g_wq_hi : g_wq_lo) + nrow * 256 + chunk * 32 + kc * 8;
        }
        CP16(dst, src, sz);
    }
}

__device__ __forceinline__ void out_stage(uint32_t smb, int stg, int chunk,
                                          int bx, int by, int w, int tid)
{
    #pragma unroll
    for (int i = 0; i < 8; i++) {
        int u = tid + i * 256;
        int tile = u >> 9;
        int uu = u & 511;
        int row = uu >> 2, kc = uu & 3;
        uint32_t dst = smb + (uint32_t)stg * STAGE_BYTES + tile * TILE_BYTES
                       + row * 80 + kc * 16;
        const __nv_bfloat16* src;
        uint32_t sz = 16;
        if (tile < 2) {
            int tok = by * 128 + row;
            size_t base = 0;
            if (tok < NTOK) base = ((size_t)w * NTOK + tok) * DIM;
            else sz = 0;
            src = (tile == 0 ? g_oh : g_ol) + base + chunk * 32 + kc * 8;
        } else {
            int nrow = bx * 128 + row;
            src = (tile == 2 ? g_wo_hi : g_wo_lo) + nrow * 256 + chunk * 32 + kc * 8;
        }
        CP16(dst, src, sz);
    }
}

// ---------------------------------------------------------------------------
// Kernel 1: QKV GEMM, cp.async 2-stage pipeline (32-col chunks, 80B rows),
// mma.sync bf16 3-pass. grid (6, 3, 256), block 256, 2 CTAs/SM.
// ---------------------------------------------------------------------------
__global__ __launch_bounds__(256, 2) void qkv_kernel()
{
    extern __shared__ char sm[];
    const uint32_t smb = smem_u32(sm);
    int* rb = (int*)(sm + SM_RB);

    const int bx = blockIdx.x;
    const int by = blockIdx.y;
    const int w  = blockIdx.z;
    const int tid = threadIdx.x;
    const int lane = tid & 31, wid = tid >> 5;
    const int wm = wid & 3, wn = wid >> 2;
    const int hx = w >> 4, wy = w & 15;

    if (tid < 128) {
        int n = by * 128 + tid;
        if (n < NTOK) {
            int l = n / 49; int rem = n - l * 49; int w1 = rem / 7; int w2 = rem - w1 * 7;
            rb[tid] = ((l * 256 + hx * 16 + wy) * 49 + w1 * 7 + w2) * 256;
        } else rb[tid] = -1;
    }
    __syncthreads();

    float acc[2][8][4];
    #pragma unroll
    for (int mt = 0; mt < 2; mt++)
        #pragma unroll
        for (int nt = 0; nt < 8; nt++)
            #pragma unroll
            for (int r = 0; r < 4; r++) acc[mt][nt][r] = 0.f;

    const int l7 = lane & 7;
    const int g = lane >> 3;
    const uint32_t arow0 = (uint32_t)(wm * 32 + (lane & 15)) * 80;
    const int acg = lane >> 4;
    const uint32_t brow0 = (uint32_t)(wn * 64 + ((g & 2) << 2) + l7) * 80;
    const int bcg = g & 1;

    qkv_stage(smb, 0, 0, rb, bx, tid);
    CP_COMMIT();

    for (int chunk = 0; chunk < 8; chunk++) {
        if (chunk < 7) {
            qkv_stage(smb, (chunk + 1) & 1, chunk + 1, rb, bx, tid);
            CP_COMMIT();
            CP_WAIT1();
        } else {
            CP_WAIT0();
        }
        __syncthreads();

        const uint32_t sb = smb + (uint32_t)(chunk & 1) * STAGE_BYTES;
        #pragma unroll
        for (int ks = 0; ks < 2; ks++) {
            uint32_t ah[2][4], al[2][4], bh[4][4], bl[4][4];
            uint32_t akc = (uint32_t)(ks * 2 + acg) << 4;
            LDSM4(ah[0], sb + T_AHI + arow0 + akc);
            LDSM4(ah[1], sb + T_AHI + arow0 + 1280 + akc);
            LDSM4(al[0], sb + T_ALO + arow0 + akc);
            LDSM4(al[1], sb + T_ALO + arow0 + 1280 + akc);
            uint32_t bkc = (uint32_t)(ks * 2 + bcg) << 4;
            #pragma unroll
            for (int p = 0; p < 4; p++) {
                LDSM4(bh[p], sb + T_BHI + brow0 + p * 1280 + bkc);
                LDSM4(bl[p], sb + T_BLO + brow0 + p * 1280 + bkc);
            }
            #pragma unroll
            for (int mt = 0; mt < 2; mt++)
                #pragma unroll
                for (int nt = 0; nt < 8; nt++) {
                    uint32_t h0 = bh[nt >> 1][(nt & 1) * 2], h1 = bh[nt >> 1][(nt & 1) * 2 + 1];
                    uint32_t lo0 = bl[nt >> 1][(nt & 1) * 2], lo1 = bl[nt >> 1][(nt & 1) * 2 + 1];
                    MMA16816(acc[mt][nt], ah[mt], h0, h1);
                    MMA16816(acc[mt][nt], al[mt], h0, h1);
                    MMA16816(acc[mt][nt], ah[mt], lo0, lo1);
                }
        }
        __syncthreads();
    }

    // ---- epilogue: split + scatter to bf16 hi/lo q/k/v ---------------------
    const int part = bx >> 1;
    __nv_bfloat16* dh_ = (part == 0) ? g_qh : (part == 1) ? g_kh : g_vh;
    __nv_bfloat16* dl_ = (part == 0) ? g_ql : (part == 1) ? g_kl : g_vl;
    const float scale = (part == 0) ? QSCALE : 1.f;
    const int trow = lane >> 2;
    const int tcol2 = (lane & 3) * 2;

    #pragma unroll
    for (int mt = 0; mt < 2; mt++) {
        #pragma unroll
        for (int half = 0; half < 2; half++) {
            int r = by * 128 + wm * 32 + mt * 16 + trow + half * 8;
            if (r >= NTOK) continue;
            #pragma unroll
            for (int nt = 0; nt < 8; nt++) {
                int o = bx * 128 + wn * 64 + nt * 8 + tcol2;
                int hh = (o & 255) >> 5, d = o & 31;
                uint32_t hip, lop;
                pack_hl(acc[mt][nt][half * 2] * scale,
                        acc[mt][nt][half * 2 + 1] * scale, hip, lop);
                size_t off = ((size_t)(w * 8 + hh) * NTOK + r) * 32 + d;
                *(uint32_t*)(dh_ + off) = hip;
                *(uint32_t*)(dl_ + off) = lop;
            }
        }
    }
}

// ---------------------------------------------------------------------------
// Kernel 2: tensor-core attention (unchanged from round 10).
// ---------------------------------------------------------------------------
__global__ __launch_bounds__(320, 2) void attn_kernel(const float* __restrict__ bias_table)
{
    extern __shared__ char sm[];
    const uint32_t smb = smem_u32(sm);
    float* bH  = (float*)(sm + A_BH);
    int*   cjs = (int*)(sm + A_CJ);

    const int wh = blockIdx.x;
    const int h  = wh & 7;
    const int w  = wh >> 3;
    const int tid = threadIdx.x;
    const int lane = tid & 31, wm = tid >> 5;
    const int t4 = lane & 3, g = lane >> 2;
    const size_t base = (size_t)wh * NTOK * DH;

    {
        const __nv_bfloat16* srcs[4] = {g_kh + base, g_kl + base, g_vh + base, g_vl + base};
        const uint32_t dsts[4] = {A_KH, A_KL, A_VH, A_VL};
        for (int idx = tid; idx < 4 * NTOKP * 4; idx += 320) {
            int arr = idx / (NTOKP * 4);
            int rem = idx - arr * (NTOKP * 4);
            int row = rem >> 2, seg = rem & 3;
            uint32_t sz = (row < NTOK) ? 16u : 0u;
            int srow = (row < NTOK) ? row : 0;
            CP16(smb + dsts[arr] + row * 80 + seg * 16, srcs[arr] + srow * 32 + seg * 8, sz);
        }
        CP_COMMIT();
        for (int i = tid; i < NBIAS; i += 320) bH[i] = bias_table[i * HEADS + h] * LOG2E;
        for (int i = tid; i < NTOKP; i += 320) {
            if (i < NTOK) {
                int l = i / 49, rem = i - l * 49, w1 = rem / 7, w2 = rem - w1 * 7;
                cjs[i] = l * 169 + w1 * 13 + w2;
            } else cjs[i] = 0;
        }
    }

    const int R = wm * 32;
    uint32_t aQh[2][2][4], aQl[2][2][4];
    #pragma unroll
    for (int mt = 0; mt < 2; mt++) {
        int r0 = R + mt * 16 + g, r1 = r0 + 8;
        #pragma unroll
        for (int kh = 0; kh < 2; kh++) {
            int c0 = kh * 16 + 2 * t4, c1 = c0 + 8;
            aQh[mt][kh][0] = (r0 < NTOK) ? *(const uint32_t*)(g_qh + base + r0 * 32 + c0) : 0u;
            aQh[mt][kh][1] = (r1 < NTOK) ? *(const uint32_t*)(g_qh + base + r1 * 32 + c0) : 0u;
            aQh[mt][kh][2] = (r0 < NTOK) ? *(const uint32_t*)(g_qh + base + r0 * 32 + c1) : 0u;
            aQh[mt][kh][3] = (r1 < NTOK) ? *(const uint32_t*)(g_qh + base + r1 * 32 + c1) : 0u;
            aQl[mt][kh][0] = (r0 < NTOK) ? *(const uint32_t*)(g_ql + base + r0 * 32 + c0) : 0u;
            aQl[mt][kh][1] = (r1 < NTOK) ? *(const uint32_t*)(g_ql + base + r1 * 32 + c0) : 0u;
            aQl[mt][kh][2] = (r0 < NTOK) ? *(const uint32_t*)(g_ql + base + r0 * 32 + c1) : 0u;
            aQl[mt][kh][3] = (r1 < NTOK) ? *(const uint32_t*)(g_ql + base + r1 * 32 + c1) : 0u;
        }
    }
    CP_WAIT0();
    __syncthreads();

    int ci[2][2];
    #pragma unroll
    for (int mt = 0; mt < 2; mt++) {
        int r0 = R + mt * 16 + g, r1 = r0 + 8;
        ci[mt][0] = cjs[r0 < NTOK ? r0 : NTOK - 1] + 929;
        ci[mt][1] = cjs[r1 < NTOK ? r1 : NTOK - 1] + 929;
    }

    float O[2][4][4];
    #pragma unroll
    for (int mt = 0; mt < 2; mt++)
        #pragma unroll
        for (int dn = 0; dn < 4; dn++)
            #pragma unroll
            for (int e = 0; e < 4; e++) O[mt][dn][e] = 0.f;
    float rs[2][2] = {{0.f, 0.f}, {0.f, 0.f}};

    const int lrow = ((lane & 8) ? 8 : 0) + (lane & 7);
    const int lcol = (lane & 16) ? 8 : 0;

    for (int j0 = 0; j0 < NTOKP; j0 += 16) {
        int   cjv[2][2];
        bool  va[2][2];
        #pragma unroll
        for (int jn = 0; jn < 2; jn++) {
            int jb = j0 + 8 * jn + 2 * t4;
            cjv[jn][0] = cjs[jb];
            cjv[jn][1] = cjs[jb + 1];
            va[jn][0] = (jb < NTOK);
            va[jn][1] = (jb + 1 < NTOK);
        }
        float bb[2][2][4];
        #pragma unroll
        for (int mt = 0; mt < 2; mt++)
            #pragma unroll
            for (int jn = 0; jn < 2; jn++) {
                bb[mt][jn][0] = bH[ci[mt][0] - cjv[jn][0]];
                bb[mt][jn][1] = bH[ci[mt][0] - cjv[jn][1]];
                bb[mt][jn][2] = bH[ci[mt][1] - cjv[jn][0]];
                bb[mt][jn][3] = bH[ci[mt][1] - cjv[jn][1]];
            }

        uint32_t bkh[2][2][2], bkl[2][2][2];
        #pragma unroll
        for (int kh = 0; kh < 2; kh++) {
            uint32_t addr = (uint32_t)((j0 + lrow) * 80 + (kh * 16 + lcol) * 2);
            uint32_t t[4];
            LDSM4(t, smb + A_KH + addr);
            bkh[0][kh][0] = t[0]; bkh[0][kh][1] = t[2];
            bkh[1][kh][0] = t[1]; bkh[1][kh][1] = t[3];
            LDSM4(t, smb + A_KL + addr);
            bkl[0][kh][0] = t[0]; bkl[0][kh][1] = t[2];
            bkl[1][kh][0] = t[1]; bkl[1][kh][1] = t[3];
        }
        uint32_t bvh[4][2], bvl[4][2];
        #pragma unroll
        for (int dh2 = 0; dh2 < 2; dh2++) {
            uint32_t addr = (uint32_t)((j0 + lrow) * 80 + (dh2 * 16 + lcol) * 2);
            uint32_t t[4];
            LDSM4T(t, smb + A_VH + addr);
            bvh[dh2 * 2][0] = t[0]; bvh[dh2 * 2][1] = t[1];
            bvh[dh2 * 2 + 1][0] = t[2]; bvh[dh2 * 2 + 1][1] = t[3];
            LDSM4T(t, smb + A_VL + addr);
            bvl[dh2 * 2][0] = t[0]; bvl[dh2 * 2][1] = t[1];
            bvl[dh2 * 2 + 1][0] = t[2]; bvl[dh2 * 2 + 1][1] = t[3];
        }

        float S[2][2][4];
        #pragma unroll
        for (int mt = 0; mt < 2; mt++)
            #pragma unroll
            for (int jn = 0; jn < 2; jn++) {
                #pragma unroll
                for (int e = 0; e < 4; e++) S[mt][jn][e] = 0.f;
                #pragma unroll
                for (int kh = 0; kh < 2; kh++) {
                    MMA16816(S[mt][jn], aQh[mt][kh], bkh[jn][kh][0], bkh[jn][kh][1]);
                    MMA16816(S[mt][jn], aQl[mt][kh], bkh[jn][kh][0], bkh[jn][kh][1]);
                    MMA16816(S[mt][jn], aQh[mt][kh], bkl[jn][kh][0], bkl[jn][kh][1]);
                }
            }

        uint32_t aPh[2][4], aPl[2][4];
        #pragma unroll
        for (int mt = 0; mt < 2; mt++) {
            float p[2][4];
            #pragma unroll
            for (int jn = 0; jn < 2; jn++) {
                #pragma unroll
                for (int e = 0; e < 4; e++) {
                    float arg = fmaf(S[mt][jn][e], LOG2E, bb[mt][jn][e]);
                    float ex; EX2F(ex, arg);
                    p[jn][e] = va[jn][e & 1] ? ex : 0.f;
                }
                rs[mt][0] += p[jn][0] + p[jn][1];
                rs[mt][1] += p[jn][2] + p[jn][3];
            }
            pack_hl(p[0][0], p[0][1], aPh[mt][0], aPl[mt][0]);
            pack_hl(p[0][2], p[0][3], aPh[mt][1], aPl[mt][1]);
            pack_hl(p[1][0], p[1][1], aPh[mt][2], aPl[mt][2]);
            pack_hl(p[1][2], p[1][3], aPh[mt][3], aPl[mt][3]);
        }

        #pragma unroll
        for (int mt = 0; mt < 2; mt++)
            #pragma unroll
            for (int dn = 0; dn < 4; dn++) {
                MMA16816(O[mt][dn], aPh[mt], bvh[dn][0], bvh[dn][1]);
                MMA16816(O[mt][dn], aPl[mt], bvh[dn][0], bvh[dn][1]);
                MMA16816(O[mt][dn], aPh[mt], bvl[dn][0], bvl[dn][1]);
            }
    }

    #pragma unroll
    for (int mt = 0; mt < 2; mt++)
        #pragma unroll
        for (int h2 = 0; h2 < 2; h2++) {
            float v = rs[mt][h2];
            v += __shfl_xor_sync(0xFFFFFFFFu, v, 1);
            v += __shfl_xor_sync(0xFFFFFFFFu, v, 2);
            rs[mt][h2] = 1.f / v;
        }
    #pragma unroll
    for (int mt = 0; mt < 2; mt++)
        #pragma unroll
        for (int h2 = 0; h2 < 2; h2++) {
            int row = R + mt * 16 + g + 8 * h2;
            if (row >= NTOK) continue;
            float inv = rs[mt][h2];
            size_t ob = ((size_t)w * NTOK + row) * DIM + h * DH;
            #pragma unroll
            for (int dn = 0; dn < 4; dn++) {
                int col = dn * 8 + 2 * t4;
                uint32_t hip, lop;
                pack_hl(O[mt][dn][h2 * 2] * inv, O[mt][dn][h2 * 2 + 1] * inv, hip, lop);
                *(uint32_t*)(g_oh + ob + col) = hip;
                *(uint32_t*)(g_ol + ob + col) = lop;
            }
        }
}

// ---------------------------------------------------------------------------
// Kernel 3: output GEMM, cp.async 2-stage pipeline (32-col chunks, 80B rows),
// mma.sync bf16 3-pass. grid (2, 3, 256), block 256, 2 CTAs/SM.
// ---------------------------------------------------------------------------
__global__ __launch_bounds__(256, 2) void out_kernel(float* __restrict__ out)
{
    extern __shared__ char sm[];
    const uint32_t smb = smem_u32(sm);

    const int bx = blockIdx.x;
    const int by = blockIdx.y;
    const int w  = blockIdx.z;
    const int tid = threadIdx.x;
    const int lane = tid & 31, wid = tid >> 5;
    const int wm = wid & 3, wn = wid >> 2;
    const int hx = w >> 4, wy = w & 15;

    float acc[2][8][4];
    #pragma unroll
    for (int mt = 0; mt < 2; mt++)
        #pragma unroll
        for (int nt = 0; nt < 8; nt++)
            #pragma unroll
            for (int r = 0; r < 4; r++) acc[mt][nt][r] = 0.f;

    const int l7 = lane & 7;
    const int g = lane >> 3;
    const uint32_t arow0 = (uint32_t)(wm * 32 + (lane & 15)) * 80;
    const int acg = lane >> 4;
    const uint32_t brow0 = (uint32_t)(wn * 64 + ((g & 2) << 2) + l7) * 80;
    const int bcg = g & 1;

    out_stage(smb, 0, 0, bx, by, w, tid);
    CP_COMMIT();

    for (int chunk = 0; chunk < 8; chunk++) {
        if (chunk < 7) {
            out_stage(smb, (chunk + 1) & 1, chunk + 1, bx, by, w, tid);
            CP_COMMIT();
            CP_WAIT1();
        } else {
            CP_WAIT0();
        }
        __syncthreads();

        const uint32_t sb = smb + (uint32_t)(chunk & 1) * STAGE_BYTES;
        #pragma unroll
        for (int ks = 0; ks < 2; ks++) {
            uint32_t ah[2][4], al[2][4], bh[4][4], bl[4][4];
            uint32_t akc = (uint32_t)(ks * 2 + acg) << 4;
            LDSM4(ah[0], sb + T_AHI + arow0 + akc);
            LDSM4(ah[1], sb + T_AHI + arow0 + 1280 + akc);
            LDSM4(al[0], sb + T_ALO + arow0 + akc);
            LDSM4(al[1], sb + T_ALO + arow0 + 1280 + akc);
            uint32_t bkc = (uint32_t)(ks * 2 + bcg) << 4;
            #pragma unroll
            for (int p = 0; p < 4; p++) {
                LDSM4(bh[p], sb + T_BHI + brow0 + p * 1280 + bkc);
                LDSM4(bl[p], sb + T_BLO + brow0 + p * 1280 + bkc);
            }
            #pragma unroll
            for (int mt = 0; mt < 2; mt++)
                #pragma unroll
                for (int nt = 0; nt < 8; nt++) {
                    uint32_t h0 = bh[nt >> 1][(nt & 1) * 2], h1 = bh[nt >> 1][(nt & 1) * 2 + 1];
                    uint32_t lo0 = bl[nt >> 1][(nt & 1) * 2], lo1 = bl[nt >> 1][(nt & 1) * 2 + 1];
                    MMA16816(acc[mt][nt], ah[mt], h0, h1);
                    MMA16816(acc[mt][nt], al[mt], h0, h1);
                    MMA16816(acc[mt][nt], ah[mt], lo0, lo1);
                }
        }
        __syncthreads();
    }

    const int trow = lane >> 2;
    const int tcol2 = (lane & 3) * 2;
    #pragma unroll
    for (int mt = 0; mt < 2; mt++) {
        #pragma unroll
        for (int half = 0; half < 2; half++) {
            int r = by * 128 + wm * 32 + mt * 16 + trow + half * 8;
            if (r >= NTOK) continue;
            int l = r / 49; int rem = r - l * 49; int w1 = rem / 7; int w2 = rem - w1 * 7;
            int ob = ((l * 256 + hx * 16 + wy) * 49 + w1 * 7 + w2) * 256;
            #pragma unroll
            for (int nt = 0; nt < 8; nt++) {
                int o = bx * 128 + wn * 64 + nt * 8 + tcol2;
                *(float2*)(out + ob + o) = make_float2(acc[mt][nt][half * 2],
                                                       acc[mt][nt][half * 2 + 1]);
            }
        }
    }
}

// ---------------------------------------------------------------------------
extern "C" void kernel_launch(void* const* d_in, const int* in_sizes, int n_in,
                              void* d_out, int out_size)
{
    const float* x    = (const float*)d_in[0];
    const float* wqkv = (const float*)d_in[1];
    const float* wout = (const float*)d_in[2];
    const float* bias = (const float*)d_in[3];
    float* out = (float*)d_out;

    cudaFuncSetAttribute(attn_kernel, cudaFuncAttributeMaxDynamicSharedMemorySize, ATTN_SMEM);
    cudaFuncSetAttribute(qkv_kernel, cudaFuncAttributeMaxDynamicSharedMemorySize, SM_GEMM_TOTAL);
    cudaFuncSetAttribute(out_kernel, cudaFuncAttributeMaxDynamicSharedMemorySize, SM_GEMM_TOTAL);

    split_x_kernel<<<(XSZ / 4 + 255) / 256, 256>>>(x);
    split_w_kernel<<<(768 * 256 / 4 + 256 * 256 / 4 + 255) / 256, 256>>>(wqkv, wout);
    qkv_kernel<<<dim3(6, 3, 256), 256, SM_GEMM_TOTAL>>>();
    attn_kernel<<<2048, 320, ATTN_SMEM>>>(bias);
    out_kernel<<<dim3(2, 3, 256), 256, SM_GEMM_TOTAL>>>(out);
}